// round 5
// baseline (speedup 1.0000x reference)
#include <cuda_runtime.h>
#include <cuda_bf16.h>
#include <math.h>
#include <stdint.h>

#define S_LEN 2048
#define D_MODEL 1024
#define N_HEADS 16
#define HEAD_DIM 64
#define FFN_DIM 4096
#define N_LAYERS 4
#define IN_DIM 64
#define OUT_DIM 128
#define DOC_LEN 256
#define N_DOCS 8
#define WIN 128

// ---------------- fp32 scratch ----------------
__device__ float g_h [S_LEN * D_MODEL];
__device__ float g_q [S_LEN * D_MODEL];
__device__ float g_k [S_LEN * D_MODEL];
__device__ float g_v [S_LEN * D_MODEL];
__device__ float g_f1[S_LEN * FFN_DIM];
__device__ float g_f3[S_LEN * FFN_DIM];

// ---------------- bf16 split planes ----------------
// transposed weights, [N][K] layout, hi+lo planes
#define OFF_WQ  0ULL
#define OFF_WK  4194304ULL
#define OFF_WV  8388608ULL
#define OFF_WO  12582912ULL
#define OFF_W1  16777216ULL
#define OFF_W3  33554432ULL
#define OFF_W2  50331648ULL
#define OFF_EMB 67108864ULL
#define OFF_OUT 67174400ULL
#define WT_TOTAL 67305472ULL
__device__ __nv_bfloat16 g_wtH[WT_TOTAL];
__device__ __nv_bfloat16 g_wtL[WT_TOTAL];

// activation planes
__device__ __nv_bfloat16 g_xH[S_LEN * IN_DIM],    g_xL[S_LEN * IN_DIM];
__device__ __nv_bfloat16 g_hnH[S_LEN * D_MODEL],  g_hnL[S_LEN * D_MODEL];
__device__ __nv_bfloat16 g_attH[S_LEN * D_MODEL], g_attL[S_LEN * D_MODEL];
__device__ __nv_bfloat16 g_f1H[S_LEN * FFN_DIM],  g_f1L[S_LEN * FFN_DIM];

__device__ __forceinline__ void bsplit(float x, __nv_bfloat16& h,
                                       __nv_bfloat16& l) {
    h = __float2bfloat16_rn(x);
    l = __float2bfloat16_rn(x - __bfloat162float(h));
}

__device__ __forceinline__ void cp_async16(uint32_t dst, const void* src) {
    asm volatile("cp.async.cg.shared.global [%0], [%1], 16;\n"
                 :: "r"(dst), "l"(src));
}
__device__ __forceinline__ void cp_commit() {
    asm volatile("cp.async.commit_group;\n");
}
template <int N_>
__device__ __forceinline__ void cp_wait() {
    asm volatile("cp.async.wait_group %0;\n" :: "n"(N_));
}
__device__ __forceinline__ void mma_bf16(float* d, const uint32_t* a,
                                         const uint32_t* b) {
    asm volatile(
        "mma.sync.aligned.m16n8k16.row.col.f32.bf16.bf16.f32 "
        "{%0,%1,%2,%3}, {%4,%5,%6,%7}, {%8,%9}, {%0,%1,%2,%3};\n"
        : "+f"(d[0]), "+f"(d[1]), "+f"(d[2]), "+f"(d[3])
        : "r"(a[0]), "r"(a[1]), "r"(a[2]), "r"(a[3]), "r"(b[0]), "r"(b[1]));
}

// ============== pre-split bf16 GEMM ==============
// C[M,N] = A[M,K] @ B^T where A planes [M][K], B planes [N][K], all bf16 hi/lo.
// CTA 128x128x16, 8 warps (2x4), warp 64x32, 3-term split product.
// smem row = 16 bf16 = 8 words + 4 pad = 12 words (48B, 16B-aligned).
#define RW 12
#define PLANE_W (128 * RW)          // 1536 words per plane per stage
#define STAGE_W (4 * PLANE_W)       // 6144 words per stage

template <bool ADD, bool BIAS>
__device__ __forceinline__ void tgemm_core(
    const __nv_bfloat16* __restrict__ AH, const __nv_bfloat16* __restrict__ AL,
    const __nv_bfloat16* __restrict__ BH, const __nv_bfloat16* __restrict__ BL,
    const float* __restrict__ bias, float* __restrict__ C,
    int M, int N, int K) {
    __shared__ uint32_t sm[2 * STAGE_W];   // 48KB

    const int tid = threadIdx.x;
    const int lane = tid & 31;
    const int w = tid >> 5;
    const int wm = w & 1;
    const int wn = w >> 1;
    const int rowBase = blockIdx.y * 128;
    const int colBase = blockIdx.x * 128;
    const int ac = lane & 3;
    const int lr = lane >> 2;

    const int prow = tid & 127;
    const int phalf = tid >> 7;           // 0/1 -> 16B chunk within row

    const __nv_bfloat16* aH = AH + (size_t)(rowBase + prow) * K + phalf * 8;
    const __nv_bfloat16* aL = AL + (size_t)(rowBase + prow) * K + phalf * 8;
    const __nv_bfloat16* bH = BH + (size_t)(colBase + prow) * K + phalf * 8;
    const __nv_bfloat16* bL = BL + (size_t)(colBase + prow) * K + phalf * 8;

    const uint32_t smBase = (uint32_t)__cvta_generic_to_shared(sm);
    const uint32_t wo = (uint32_t)(prow * RW + phalf * 4) * 4;

    auto load_stage = [&](int st, int k0) {
        uint32_t b = smBase + (uint32_t)st * (STAGE_W * 4);
        cp_async16(b + wo, aH + k0);
        cp_async16(b + PLANE_W * 4 + wo, aL + k0);
        cp_async16(b + 2 * PLANE_W * 4 + wo, bH + k0);
        cp_async16(b + 3 * PLANE_W * 4 + wo, bL + k0);
    };

    float acc[4][4][4];
#pragma unroll
    for (int i = 0; i < 4; i++)
#pragma unroll
        for (int j = 0; j < 4; j++)
#pragma unroll
            for (int t = 0; t < 4; t++) acc[i][j][t] = 0.f;

    const int iters = K >> 4;
    load_stage(0, 0);
    cp_commit();

    for (int s = 0; s < iters; ++s) {
        cp_wait<0>();
        __syncthreads();
        if (s + 1 < iters) load_stage((s + 1) & 1, (s + 1) << 4);
        cp_commit();

        const uint32_t* ash = sm + (s & 1) * STAGE_W;
        const uint32_t* asl = ash + PLANE_W;
        const uint32_t* bsh = ash + 2 * PLANE_W;
        const uint32_t* bsl = ash + 3 * PLANE_W;

        uint32_t bh[4][2], bl[4][2];
#pragma unroll
        for (int j = 0; j < 4; j++) {
            int n = wn * 32 + j * 8 + lr;
            int w0 = n * RW + ac;
            bh[j][0] = bsh[w0]; bh[j][1] = bsh[w0 + 4];
            bl[j][0] = bsl[w0]; bl[j][1] = bsl[w0 + 4];
        }
#pragma unroll
        for (int i = 0; i < 4; i++) {
            int r = wm * 64 + i * 16 + lr;
            int w0 = r * RW + ac;
            int w1 = (r + 8) * RW + ac;
            uint32_t ah[4] = { ash[w0], ash[w1], ash[w0 + 4], ash[w1 + 4] };
            uint32_t al[4] = { asl[w0], asl[w1], asl[w0 + 4], asl[w1 + 4] };
#pragma unroll
            for (int j = 0; j < 4; j++) {
                mma_bf16(acc[i][j], al, bh[j]);
                mma_bf16(acc[i][j], ah, bl[j]);
                mma_bf16(acc[i][j], ah, bh[j]);
            }
        }
    }

    // epilogue
#pragma unroll
    for (int i = 0; i < 4; i++) {
        int r0 = rowBase + wm * 64 + i * 16 + lr;
#pragma unroll
        for (int j = 0; j < 4; j++) {
            int c0 = colBase + wn * 32 + j * 8 + ac * 2;
            float2 v0 = make_float2(acc[i][j][0], acc[i][j][1]);
            float2 v1 = make_float2(acc[i][j][2], acc[i][j][3]);
            if (BIAS) {
                float b0 = bias[c0], b1 = bias[c0 + 1];
                v0.x += b0; v0.y += b1; v1.x += b0; v1.y += b1;
            }
            float* p0 = C + (size_t)r0 * N + c0;
            float* p1 = C + (size_t)(r0 + 8) * N + c0;
            if (ADD) {
                float2 o0 = *(float2*)p0, o1 = *(float2*)p1;
                v0.x += o0.x; v0.y += o0.y;
                v1.x += o1.x; v1.y += o1.y;
            }
            *(float2*)p0 = v0;
            *(float2*)p1 = v1;
        }
    }
}

template <bool ADD, bool BIAS>
__global__ __launch_bounds__(256)
void tgemm_kernel(const __nv_bfloat16* AH, const __nv_bfloat16* AL,
                  const __nv_bfloat16* BH, const __nv_bfloat16* BL,
                  const float* bias, float* C, int M, int N, int K) {
    tgemm_core<ADD, BIAS>(AH, AL, BH, BL, bias, C, M, N, K);
}

// fused QKV (z selects weight/output)
__global__ __launch_bounds__(256)
void qkv_kernel(const __nv_bfloat16* AH, const __nv_bfloat16* AL,
                size_t wOffQ, size_t wOffK, size_t wOffV,
                float* q, float* k, float* v) {
    size_t off = (blockIdx.z == 0) ? wOffQ : (blockIdx.z == 1) ? wOffK : wOffV;
    float* C = (blockIdx.z == 0) ? q : (blockIdx.z == 1) ? k : v;
    tgemm_core<false, false>(AH, AL, g_wtH + off, g_wtL + off, nullptr, C,
                             S_LEN, D_MODEL, D_MODEL);
}

// fused W1/W3 (z selects)
__global__ __launch_bounds__(256)
void w13_kernel(const __nv_bfloat16* AH, const __nv_bfloat16* AL,
                size_t wOff1, size_t wOff3, float* f1, float* f3) {
    size_t off = (blockIdx.z == 0) ? wOff1 : wOff3;
    float* C = (blockIdx.z == 0) ? f1 : f3;
    tgemm_core<false, false>(AH, AL, g_wtH + off, g_wtL + off, nullptr, C,
                             S_LEN, FFN_DIM, D_MODEL);
}

// ---------------- weight transpose + split prepass ----------------
// src W [K,N] fp32 (layer stride srcStride) -> dst planes [N,K] (dstStride)
__global__ void transpose_split(const float* __restrict__ src,
                                __nv_bfloat16* __restrict__ dH,
                                __nv_bfloat16* __restrict__ dL,
                                int K, int N, size_t srcStride,
                                size_t dstStride) {
    src += (size_t)blockIdx.z * srcStride;
    dH += (size_t)blockIdx.z * dstStride;
    dL += (size_t)blockIdx.z * dstStride;
    __shared__ float t[32][33];
    int x = blockIdx.x * 32 + threadIdx.x;      // N index
    int y0 = blockIdx.y * 32;                   // K base
#pragma unroll
    for (int i = 0; i < 32; i += 8)
        t[threadIdx.y + i][threadIdx.x] =
            src[(size_t)(y0 + threadIdx.y + i) * N + x];
    __syncthreads();
    int n = blockIdx.x * 32 + threadIdx.y;
    int kk = y0 + threadIdx.x;
#pragma unroll
    for (int i = 0; i < 32; i += 8) {
        float v = t[threadIdx.x][threadIdx.y + i];
        __nv_bfloat16 h, l;
        bsplit(v, h, l);
        size_t o = (size_t)(n + i) * K + kk;
        dH[o] = h;
        dL[o] = l;
    }
}

// ---------------- x split ----------------
__global__ __launch_bounds__(256)
void x_split_kernel(const float* __restrict__ x) {
    int i = blockIdx.x * 256 + threadIdx.x;
    if (i < S_LEN * IN_DIM) {
        __nv_bfloat16 h, l;
        bsplit(x[i], h, l);
        g_xH[i] = h;
        g_xL[i] = l;
    }
}

// ---------------- RMSNorm -> split planes ----------------
__global__ __launch_bounds__(256)
void rmsnorm_split_kernel(const float* __restrict__ x,
                          const float* __restrict__ w,
                          __nv_bfloat16* __restrict__ yH,
                          __nv_bfloat16* __restrict__ yL) {
    int row = blockIdx.x;
    const float* xr = x + (size_t)row * D_MODEL;
    float s = 0.f;
    for (int i = threadIdx.x; i < D_MODEL; i += 256) {
        float v = xr[i];
        s += v * v;
    }
    __shared__ float red[8];
#pragma unroll
    for (int o = 16; o; o >>= 1) s += __shfl_xor_sync(0xffffffffu, s, o);
    if ((threadIdx.x & 31) == 0) red[threadIdx.x >> 5] = s;
    __syncthreads();
    if (threadIdx.x < 8) {
        float t = red[threadIdx.x];
#pragma unroll
        for (int o = 4; o; o >>= 1) t += __shfl_xor_sync(0xffu, t, o);
        if (threadIdx.x == 0) red[0] = rsqrtf(t / (float)D_MODEL + 1e-5f);
    }
    __syncthreads();
    float r = red[0];
    for (int i = threadIdx.x; i < D_MODEL; i += 256) {
        float v = xr[i] * r * w[i];
        __nv_bfloat16 h, l;
        bsplit(v, h, l);
        yH[(size_t)row * D_MODEL + i] = h;
        yL[(size_t)row * D_MODEL + i] = l;
    }
}

// ---------------- RoPE (in place on q and k) ----------------
__global__ __launch_bounds__(256)
void rope_kernel(float* __restrict__ q, float* __restrict__ k,
                 const int* __restrict__ tok_id) {
    int idx = blockIdx.x * 256 + threadIdx.x;
    if (idx >= S_LEN * N_HEADS * (HEAD_DIM / 2)) return;
    int j = idx & 31;
    int h = (idx >> 5) & 15;
    int s = idx >> 9;
    float t = (float)tok_id[s];
    float inv = expf(-logf(10000.f) * (float)(2 * j) / (float)HEAD_DIM);
    float ang = t * inv;
    float c = cosf(ang), sn = sinf(ang);
    int base = s * D_MODEL + h * HEAD_DIM + j;
    float q1 = q[base], q2 = q[base + 32];
    q[base] = q1 * c - q2 * sn;
    q[base + 32] = q1 * sn + q2 * c;
    float k1 = k[base], k2 = k[base + 32];
    k[base] = k1 * c - k2 * sn;
    k[base + 32] = k1 * sn + k2 * c;
}

// ---------------- attention -> split planes ----------------
__global__ __launch_bounds__(256)
void attention_kernel(const float* __restrict__ q, const float* __restrict__ k,
                      const float* __restrict__ v,
                      __nv_bfloat16* __restrict__ outH,
                      __nv_bfloat16* __restrict__ outL) {
    const int doc = blockIdx.x;
    const int head = blockIdx.y;
    const int qi = threadIdx.x;
    const int qg = doc * DOC_LEN + qi;

    __shared__ float Ks[64][64];
    __shared__ float Vs[64][64];

    float qreg[HEAD_DIM];
    const float scale = 0.125f;
    const float* qp = q + (size_t)qg * D_MODEL + head * HEAD_DIM;
#pragma unroll
    for (int d = 0; d < HEAD_DIM; d += 4) {
        float4 t = *(const float4*)&qp[d];
        qreg[d] = t.x * scale; qreg[d + 1] = t.y * scale;
        qreg[d + 2] = t.z * scale; qreg[d + 3] = t.w * scale;
    }

    float o[HEAD_DIM];
#pragma unroll
    for (int d = 0; d < HEAD_DIM; d++) o[d] = 0.f;
    float m = -1e30f, l = 0.f;

    for (int kt = 0; kt < 4; kt++) {
        __syncthreads();
        for (int f = threadIdx.x; f < 1024; f += 256) {
            int r = f >> 4;
            int c = (f & 15) << 2;
            int kg = doc * DOC_LEN + kt * 64 + r;
            *(float4*)&Ks[r][c] =
                *(const float4*)&k[(size_t)kg * D_MODEL + head * HEAD_DIM + c];
            *(float4*)&Vs[r][c] =
                *(const float4*)&v[(size_t)kg * D_MODEL + head * HEAD_DIM + c];
        }
        __syncthreads();

        for (int j = 0; j < 64; j++) {
            int tk = kt * 64 + j;
            int dlt = qi - tk;
            if (dlt < 0) dlt = -dlt;
            if (dlt < WIN) {
                float s = 0.f;
#pragma unroll
                for (int d = 0; d < HEAD_DIM; d++) s += qreg[d] * Ks[j][d];
                float mn = fmaxf(m, s);
                float corr = expf(m - mn);
                float p = expf(s - mn);
                l = l * corr + p;
#pragma unroll
                for (int d = 0; d < HEAD_DIM; d++)
                    o[d] = o[d] * corr + p * Vs[j][d];
                m = mn;
            }
        }
    }

    float invl = 1.f / l;
    size_t base = (size_t)qg * D_MODEL + head * HEAD_DIM;
#pragma unroll
    for (int d = 0; d < HEAD_DIM; d++) {
        __nv_bfloat16 h, lo;
        bsplit(o[d] * invl, h, lo);
        outH[base + d] = h;
        outL[base + d] = lo;
    }
}

// ---------------- SwiGLU -> split planes ----------------
__global__ __launch_bounds__(256)
void silu_mul_kernel(const float* __restrict__ f1, const float* __restrict__ f3,
                     __nv_bfloat16* __restrict__ oH,
                     __nv_bfloat16* __restrict__ oL, int n4) {
    int i = blockIdx.x * 256 + threadIdx.x;
    if (i < n4) {
        float4 a = ((const float4*)f1)[i];
        float4 b = ((const float4*)f3)[i];
        float r[4];
        r[0] = (a.x / (1.f + expf(-a.x))) * b.x;
        r[1] = (a.y / (1.f + expf(-a.y))) * b.y;
        r[2] = (a.z / (1.f + expf(-a.z))) * b.z;
        r[3] = (a.w / (1.f + expf(-a.w))) * b.w;
#pragma unroll
        for (int t = 0; t < 4; t++) {
            __nv_bfloat16 h, l;
            bsplit(r[t], h, l);
            oH[i * 4 + t] = h;
            oL[i * 4 + t] = l;
        }
    }
}

// ---------------- host orchestration ----------------
extern "C" void kernel_launch(void* const* d_in, const int* in_sizes, int n_in,
                              void* d_out, int out_size) {
    const float* x           = (const float*)d_in[0];
    const float* emb_w       = (const float*)d_in[1];
    const float* emb_b       = (const float*)d_in[2];
    const float* wq          = (const float*)d_in[3];
    const float* wk          = (const float*)d_in[4];
    const float* wv          = (const float*)d_in[5];
    const float* wo          = (const float*)d_in[6];
    const float* attn_norm_w = (const float*)d_in[7];
    const float* ffn_norm_w  = (const float*)d_in[8];
    const float* w1          = (const float*)d_in[9];
    const float* w2          = (const float*)d_in[10];
    const float* w3          = (const float*)d_in[11];
    const float* out_norm_w  = (const float*)d_in[12];
    const float* out_w       = (const float*)d_in[13];
    const int*   tok_id      = (const int*)d_in[15];
    float* out = (float*)d_out;

    float *h, *q, *k, *v, *f1, *f3;
    cudaGetSymbolAddress((void**)&h, g_h);
    cudaGetSymbolAddress((void**)&q, g_q);
    cudaGetSymbolAddress((void**)&k, g_k);
    cudaGetSymbolAddress((void**)&v, g_v);
    cudaGetSymbolAddress((void**)&f1, g_f1);
    cudaGetSymbolAddress((void**)&f3, g_f3);
    __nv_bfloat16 *wtH, *wtL, *xH, *xL, *hnH, *hnL, *attH, *attL, *f1H, *f1L;
    cudaGetSymbolAddress((void**)&wtH, g_wtH);
    cudaGetSymbolAddress((void**)&wtL, g_wtL);
    cudaGetSymbolAddress((void**)&xH, g_xH);
    cudaGetSymbolAddress((void**)&xL, g_xL);
    cudaGetSymbolAddress((void**)&hnH, g_hnH);
    cudaGetSymbolAddress((void**)&hnL, g_hnL);
    cudaGetSymbolAddress((void**)&attH, g_attH);
    cudaGetSymbolAddress((void**)&attL, g_attL);
    cudaGetSymbolAddress((void**)&f1H, g_f1H);
    cudaGetSymbolAddress((void**)&f1L, g_f1L);

    dim3 tb(32, 8);
    // weight prepass: transpose + split
    transpose_split<<<dim3(32, 32, 4), tb>>>(wq, wtH + OFF_WQ, wtL + OFF_WQ,
        D_MODEL, D_MODEL, (size_t)D_MODEL * D_MODEL, 1048576ULL);
    transpose_split<<<dim3(32, 32, 4), tb>>>(wk, wtH + OFF_WK, wtL + OFF_WK,
        D_MODEL, D_MODEL, (size_t)D_MODEL * D_MODEL, 1048576ULL);
    transpose_split<<<dim3(32, 32, 4), tb>>>(wv, wtH + OFF_WV, wtL + OFF_WV,
        D_MODEL, D_MODEL, (size_t)D_MODEL * D_MODEL, 1048576ULL);
    transpose_split<<<dim3(32, 32, 4), tb>>>(wo, wtH + OFF_WO, wtL + OFF_WO,
        D_MODEL, D_MODEL, (size_t)D_MODEL * D_MODEL, 1048576ULL);
    transpose_split<<<dim3(128, 32, 4), tb>>>(w1, wtH + OFF_W1, wtL + OFF_W1,
        D_MODEL, FFN_DIM, (size_t)D_MODEL * FFN_DIM, 4194304ULL);
    transpose_split<<<dim3(128, 32, 4), tb>>>(w3, wtH + OFF_W3, wtL + OFF_W3,
        D_MODEL, FFN_DIM, (size_t)D_MODEL * FFN_DIM, 4194304ULL);
    transpose_split<<<dim3(32, 128, 4), tb>>>(w2, wtH + OFF_W2, wtL + OFF_W2,
        FFN_DIM, D_MODEL, (size_t)FFN_DIM * D_MODEL, 4194304ULL);
    transpose_split<<<dim3(32, 2, 1), tb>>>(emb_w, wtH + OFF_EMB,
        wtL + OFF_EMB, IN_DIM, D_MODEL, 0ULL, 0ULL);
    transpose_split<<<dim3(4, 32, 1), tb>>>(out_w, wtH + OFF_OUT,
        wtL + OFF_OUT, D_MODEL, OUT_DIM, 0ULL, 0ULL);

    x_split_kernel<<<(S_LEN * IN_DIM + 255) / 256, 256>>>(x);

    // embed: h = x @ emb_w + emb_b
    tgemm_kernel<false, true><<<dim3(D_MODEL / 128, S_LEN / 128), 256>>>(
        xH, xL, wtH + OFF_EMB, wtL + OFF_EMB, emb_b, h,
        S_LEN, D_MODEL, IN_DIM);

    for (int l = 0; l < N_LAYERS; l++) {
        size_t oq = OFF_WQ + (size_t)l * 1048576;
        size_t ok = OFF_WK + (size_t)l * 1048576;
        size_t ov = OFF_WV + (size_t)l * 1048576;
        size_t oo = OFF_WO + (size_t)l * 1048576;
        size_t o1 = OFF_W1 + (size_t)l * 4194304;
        size_t o3 = OFF_W3 + (size_t)l * 4194304;
        size_t o2 = OFF_W2 + (size_t)l * 4194304;

        rmsnorm_split_kernel<<<S_LEN, 256>>>(h, attn_norm_w + l * D_MODEL,
                                             hnH, hnL);

        qkv_kernel<<<dim3(D_MODEL / 128, S_LEN / 128, 3), 256>>>(
            hnH, hnL, oq, ok, ov, q, k, v);

        rope_kernel<<<(S_LEN * N_HEADS * 32) / 256, 256>>>(q, k, tok_id);

        attention_kernel<<<dim3(N_DOCS, N_HEADS), 256>>>(q, k, v, attH, attL);

        tgemm_kernel<true, false><<<dim3(D_MODEL / 128, S_LEN / 128), 256>>>(
            attH, attL, wtH + oo, wtL + oo, nullptr, h,
            S_LEN, D_MODEL, D_MODEL);

        rmsnorm_split_kernel<<<S_LEN, 256>>>(h, ffn_norm_w + l * D_MODEL,
                                             hnH, hnL);

        w13_kernel<<<dim3(FFN_DIM / 128, S_LEN / 128, 2), 256>>>(
            hnH, hnL, o1, o3, f1, f3);

        silu_mul_kernel<<<(S_LEN * FFN_DIM / 4 + 255) / 256, 256>>>(
            f1, f3, f1H, f1L, S_LEN * FFN_DIM / 4);

        tgemm_kernel<true, false><<<dim3(D_MODEL / 128, S_LEN / 128), 256>>>(
            f1H, f1L, wtH + o2, wtL + o2, nullptr, h,
            S_LEN, D_MODEL, FFN_DIM);
    }

    rmsnorm_split_kernel<<<S_LEN, 256>>>(h, out_norm_w, hnH, hnL);
    tgemm_kernel<false, false><<<dim3(OUT_DIM / 128, S_LEN / 128), 256>>>(
        hnH, hnL, wtH + OFF_OUT, wtL + OFF_OUT, nullptr, out,
        S_LEN, OUT_DIM, D_MODEL);
}

// round 6
// speedup vs baseline: 1.0024x; 1.0024x over previous
#include <cuda_runtime.h>
#include <cuda_bf16.h>
#include <math.h>
#include <stdint.h>

#define S_LEN 2048
#define D_MODEL 1024
#define N_HEADS 16
#define HEAD_DIM 64
#define FFN_DIM 4096
#define N_LAYERS 4
#define IN_DIM 64
#define OUT_DIM 128
#define DOC_LEN 256
#define N_DOCS 8
#define WIN 128

// ---------------- fp32 scratch ----------------
__device__ float g_h [S_LEN * D_MODEL];
__device__ float g_q [S_LEN * D_MODEL];
__device__ float g_k [S_LEN * D_MODEL];
__device__ float g_v [S_LEN * D_MODEL];
__device__ float g_f1[S_LEN * FFN_DIM];
__device__ float g_f3[S_LEN * FFN_DIM];

// ---------------- bf16 split planes ----------------
// transposed weights, [N][K] layout, hi+lo planes
#define OFF_WQ  0ULL
#define OFF_WK  4194304ULL
#define OFF_WV  8388608ULL
#define OFF_WO  12582912ULL
#define OFF_W1  16777216ULL
#define OFF_W3  33554432ULL
#define OFF_W2  50331648ULL
#define OFF_EMB 67108864ULL
#define OFF_OUT 67174400ULL
#define WT_TOTAL 67305472ULL
__device__ __nv_bfloat16 g_wtH[WT_TOTAL];
__device__ __nv_bfloat16 g_wtL[WT_TOTAL];

// activation planes
__device__ __nv_bfloat16 g_xH[S_LEN * IN_DIM],    g_xL[S_LEN * IN_DIM];
__device__ __nv_bfloat16 g_hnH[S_LEN * D_MODEL],  g_hnL[S_LEN * D_MODEL];
__device__ __nv_bfloat16 g_attH[S_LEN * D_MODEL], g_attL[S_LEN * D_MODEL];
__device__ __nv_bfloat16 g_f1H[S_LEN * FFN_DIM],  g_f1L[S_LEN * FFN_DIM];

__device__ __forceinline__ void bsplit(float x, __nv_bfloat16& h,
                                       __nv_bfloat16& l) {
    h = __float2bfloat16_rn(x);
    l = __float2bfloat16_rn(x - __bfloat162float(h));
}

__device__ __forceinline__ void cp_async16(uint32_t dst, const void* src) {
    asm volatile("cp.async.cg.shared.global [%0], [%1], 16;\n"
                 :: "r"(dst), "l"(src));
}
__device__ __forceinline__ void cp_commit() {
    asm volatile("cp.async.commit_group;\n");
}
template <int N_>
__device__ __forceinline__ void cp_wait() {
    asm volatile("cp.async.wait_group %0;\n" :: "n"(N_));
}
__device__ __forceinline__ void mma_bf16(float* d, const uint32_t* a,
                                         const uint32_t* b) {
    asm volatile(
        "mma.sync.aligned.m16n8k16.row.col.f32.bf16.bf16.f32 "
        "{%0,%1,%2,%3}, {%4,%5,%6,%7}, {%8,%9}, {%0,%1,%2,%3};\n"
        : "+f"(d[0]), "+f"(d[1]), "+f"(d[2]), "+f"(d[3])
        : "r"(a[0]), "r"(a[1]), "r"(a[2]), "r"(a[3]), "r"(b[0]), "r"(b[1]));
}

// ============== pre-split bf16 GEMM ==============
// C[M,N] = A[M,K] @ B^T where A planes [M][K], B planes [N][K], all bf16 hi/lo.
// CTA 128x128x16, 8 warps (2x4), warp 64x32, 3-term split product.
// smem row = 16 bf16 = 8 words + 4 pad = 12 words (48B, 16B-aligned).
#define RW 12
#define PLANE_W (128 * RW)          // 1536 words per plane per stage
#define STAGE_W (4 * PLANE_W)       // 6144 words per stage

template <bool ADD, bool BIAS>
__device__ __forceinline__ void tgemm_core(
    const __nv_bfloat16* __restrict__ AH, const __nv_bfloat16* __restrict__ AL,
    const __nv_bfloat16* __restrict__ BH, const __nv_bfloat16* __restrict__ BL,
    const float* __restrict__ bias, float* __restrict__ C,
    int M, int N, int K) {
    __shared__ uint32_t sm[2 * STAGE_W];   // 48KB

    const int tid = threadIdx.x;
    const int lane = tid & 31;
    const int w = tid >> 5;
    const int wm = w & 1;
    const int wn = w >> 1;
    const int rowBase = blockIdx.y * 128;
    const int colBase = blockIdx.x * 128;
    const int ac = lane & 3;
    const int lr = lane >> 2;

    const int prow = tid & 127;
    const int phalf = tid >> 7;           // 0/1 -> 16B chunk within row

    const __nv_bfloat16* aH = AH + (size_t)(rowBase + prow) * K + phalf * 8;
    const __nv_bfloat16* aL = AL + (size_t)(rowBase + prow) * K + phalf * 8;
    const __nv_bfloat16* bH = BH + (size_t)(colBase + prow) * K + phalf * 8;
    const __nv_bfloat16* bL = BL + (size_t)(colBase + prow) * K + phalf * 8;

    const uint32_t smBase = (uint32_t)__cvta_generic_to_shared(sm);
    const uint32_t wo = (uint32_t)(prow * RW + phalf * 4) * 4;

    auto load_stage = [&](int st, int k0) {
        uint32_t b = smBase + (uint32_t)st * (STAGE_W * 4);
        cp_async16(b + wo, aH + k0);
        cp_async16(b + PLANE_W * 4 + wo, aL + k0);
        cp_async16(b + 2 * PLANE_W * 4 + wo, bH + k0);
        cp_async16(b + 3 * PLANE_W * 4 + wo, bL + k0);
    };

    float acc[4][4][4];
#pragma unroll
    for (int i = 0; i < 4; i++)
#pragma unroll
        for (int j = 0; j < 4; j++)
#pragma unroll
            for (int t = 0; t < 4; t++) acc[i][j][t] = 0.f;

    const int iters = K >> 4;
    load_stage(0, 0);
    cp_commit();

    for (int s = 0; s < iters; ++s) {
        cp_wait<0>();
        __syncthreads();
        if (s + 1 < iters) load_stage((s + 1) & 1, (s + 1) << 4);
        cp_commit();

        const uint32_t* ash = sm + (s & 1) * STAGE_W;
        const uint32_t* asl = ash + PLANE_W;
        const uint32_t* bsh = ash + 2 * PLANE_W;
        const uint32_t* bsl = ash + 3 * PLANE_W;

        uint32_t bh[4][2], bl[4][2];
#pragma unroll
        for (int j = 0; j < 4; j++) {
            int n = wn * 32 + j * 8 + lr;
            int w0 = n * RW + ac;
            bh[j][0] = bsh[w0]; bh[j][1] = bsh[w0 + 4];
            bl[j][0] = bsl[w0]; bl[j][1] = bsl[w0 + 4];
        }
#pragma unroll
        for (int i = 0; i < 4; i++) {
            int r = wm * 64 + i * 16 + lr;
            int w0 = r * RW + ac;
            int w1 = (r + 8) * RW + ac;
            uint32_t ah[4] = { ash[w0], ash[w1], ash[w0 + 4], ash[w1 + 4] };
            uint32_t al[4] = { asl[w0], asl[w1], asl[w0 + 4], asl[w1 + 4] };
#pragma unroll
            for (int j = 0; j < 4; j++) {
                mma_bf16(acc[i][j], al, bh[j]);
                mma_bf16(acc[i][j], ah, bl[j]);
                mma_bf16(acc[i][j], ah, bh[j]);
            }
        }
    }

    // epilogue
#pragma unroll
    for (int i = 0; i < 4; i++) {
        int r0 = rowBase + wm * 64 + i * 16 + lr;
#pragma unroll
        for (int j = 0; j < 4; j++) {
            int c0 = colBase + wn * 32 + j * 8 + ac * 2;
            float2 v0 = make_float2(acc[i][j][0], acc[i][j][1]);
            float2 v1 = make_float2(acc[i][j][2], acc[i][j][3]);
            if (BIAS) {
                float b0 = bias[c0], b1 = bias[c0 + 1];
                v0.x += b0; v0.y += b1; v1.x += b0; v1.y += b1;
            }
            float* p0 = C + (size_t)r0 * N + c0;
            float* p1 = C + (size_t)(r0 + 8) * N + c0;
            if (ADD) {
                float2 o0 = *(float2*)p0, o1 = *(float2*)p1;
                v0.x += o0.x; v0.y += o0.y;
                v1.x += o1.x; v1.y += o1.y;
            }
            *(float2*)p0 = v0;
            *(float2*)p1 = v1;
        }
    }
}

template <bool ADD, bool BIAS>
__global__ __launch_bounds__(256)
void tgemm_kernel(const __nv_bfloat16* AH, const __nv_bfloat16* AL,
                  const __nv_bfloat16* BH, const __nv_bfloat16* BL,
                  const float* bias, float* C, int M, int N, int K) {
    tgemm_core<ADD, BIAS>(AH, AL, BH, BL, bias, C, M, N, K);
}

// fused QKV (z selects weight/output)
__global__ __launch_bounds__(256)
void qkv_kernel(const __nv_bfloat16* AH, const __nv_bfloat16* AL,
                size_t wOffQ, size_t wOffK, size_t wOffV,
                float* q, float* k, float* v) {
    size_t off = (blockIdx.z == 0) ? wOffQ : (blockIdx.z == 1) ? wOffK : wOffV;
    float* C = (blockIdx.z == 0) ? q : (blockIdx.z == 1) ? k : v;
    tgemm_core<false, false>(AH, AL, g_wtH + off, g_wtL + off, nullptr, C,
                             S_LEN, D_MODEL, D_MODEL);
}

// fused W1/W3 (z selects)
__global__ __launch_bounds__(256)
void w13_kernel(const __nv_bfloat16* AH, const __nv_bfloat16* AL,
                size_t wOff1, size_t wOff3, float* f1, float* f3) {
    size_t off = (blockIdx.z == 0) ? wOff1 : wOff3;
    float* C = (blockIdx.z == 0) ? f1 : f3;
    tgemm_core<false, false>(AH, AL, g_wtH + off, g_wtL + off, nullptr, C,
                             S_LEN, FFN_DIM, D_MODEL);
}

// ---------------- weight transpose + split prepass ----------------
// src W [K,N] fp32 (layer stride srcStride) -> dst planes [N,K] (dstStride)
__global__ void transpose_split(const float* __restrict__ src,
                                __nv_bfloat16* __restrict__ dH,
                                __nv_bfloat16* __restrict__ dL,
                                int K, int N, size_t srcStride,
                                size_t dstStride) {
    src += (size_t)blockIdx.z * srcStride;
    dH += (size_t)blockIdx.z * dstStride;
    dL += (size_t)blockIdx.z * dstStride;
    __shared__ float t[32][33];
    int x = blockIdx.x * 32 + threadIdx.x;      // N index
    int y0 = blockIdx.y * 32;                   // K base
#pragma unroll
    for (int i = 0; i < 32; i += 8)
        t[threadIdx.y + i][threadIdx.x] =
            src[(size_t)(y0 + threadIdx.y + i) * N + x];
    __syncthreads();
    int n = blockIdx.x * 32 + threadIdx.y;
    int kk = y0 + threadIdx.x;
#pragma unroll
    for (int i = 0; i < 32; i += 8) {
        float v = t[threadIdx.x][threadIdx.y + i];
        __nv_bfloat16 h, l;
        bsplit(v, h, l);
        size_t o = (size_t)(n + i) * K + kk;
        dH[o] = h;
        dL[o] = l;
    }
}

// ---------------- x split ----------------
__global__ __launch_bounds__(256)
void x_split_kernel(const float* __restrict__ x) {
    int i = blockIdx.x * 256 + threadIdx.x;
    if (i < S_LEN * IN_DIM) {
        __nv_bfloat16 h, l;
        bsplit(x[i], h, l);
        g_xH[i] = h;
        g_xL[i] = l;
    }
}

// ---------------- RMSNorm -> split planes ----------------
__global__ __launch_bounds__(256)
void rmsnorm_split_kernel(const float* __restrict__ x,
                          const float* __restrict__ w,
                          __nv_bfloat16* __restrict__ yH,
                          __nv_bfloat16* __restrict__ yL) {
    int row = blockIdx.x;
    const float* xr = x + (size_t)row * D_MODEL;
    float s = 0.f;
    for (int i = threadIdx.x; i < D_MODEL; i += 256) {
        float v = xr[i];
        s += v * v;
    }
    __shared__ float red[8];
#pragma unroll
    for (int o = 16; o; o >>= 1) s += __shfl_xor_sync(0xffffffffu, s, o);
    if ((threadIdx.x & 31) == 0) red[threadIdx.x >> 5] = s;
    __syncthreads();
    if (threadIdx.x < 8) {
        float t = red[threadIdx.x];
#pragma unroll
        for (int o = 4; o; o >>= 1) t += __shfl_xor_sync(0xffu, t, o);
        if (threadIdx.x == 0) red[0] = rsqrtf(t / (float)D_MODEL + 1e-5f);
    }
    __syncthreads();
    float r = red[0];
    for (int i = threadIdx.x; i < D_MODEL; i += 256) {
        float v = xr[i] * r * w[i];
        __nv_bfloat16 h, l;
        bsplit(v, h, l);
        yH[(size_t)row * D_MODEL + i] = h;
        yL[(size_t)row * D_MODEL + i] = l;
    }
}

// ---------------- RoPE (in place on q and k) ----------------
__global__ __launch_bounds__(256)
void rope_kernel(float* __restrict__ q, float* __restrict__ k,
                 const int* __restrict__ tok_id) {
    int idx = blockIdx.x * 256 + threadIdx.x;
    if (idx >= S_LEN * N_HEADS * (HEAD_DIM / 2)) return;
    int j = idx & 31;
    int h = (idx >> 5) & 15;
    int s = idx >> 9;
    float t = (float)tok_id[s];
    float inv = expf(-logf(10000.f) * (float)(2 * j) / (float)HEAD_DIM);
    float ang = t * inv;
    float c = cosf(ang), sn = sinf(ang);
    int base = s * D_MODEL + h * HEAD_DIM + j;
    float q1 = q[base], q2 = q[base + 32];
    q[base] = q1 * c - q2 * sn;
    q[base + 32] = q1 * sn + q2 * c;
    float k1 = k[base], k2 = k[base + 32];
    k[base] = k1 * c - k2 * sn;
    k[base + 32] = k1 * sn + k2 * c;
}

// ---------------- attention -> split planes ----------------
__global__ __launch_bounds__(256)
void attention_kernel(const float* __restrict__ q, const float* __restrict__ k,
                      const float* __restrict__ v,
                      __nv_bfloat16* __restrict__ outH,
                      __nv_bfloat16* __restrict__ outL) {
    const int doc = blockIdx.x;
    const int head = blockIdx.y;
    const int qi = threadIdx.x;
    const int qg = doc * DOC_LEN + qi;

    __shared__ float Ks[64][64];
    __shared__ float Vs[64][64];

    float qreg[HEAD_DIM];
    const float scale = 0.125f;
    const float* qp = q + (size_t)qg * D_MODEL + head * HEAD_DIM;
#pragma unroll
    for (int d = 0; d < HEAD_DIM; d += 4) {
        float4 t = *(const float4*)&qp[d];
        qreg[d] = t.x * scale; qreg[d + 1] = t.y * scale;
        qreg[d + 2] = t.z * scale; qreg[d + 3] = t.w * scale;
    }

    float o[HEAD_DIM];
#pragma unroll
    for (int d = 0; d < HEAD_DIM; d++) o[d] = 0.f;
    float m = -1e30f, l = 0.f;

    for (int kt = 0; kt < 4; kt++) {
        __syncthreads();
        for (int f = threadIdx.x; f < 1024; f += 256) {
            int r = f >> 4;
            int c = (f & 15) << 2;
            int kg = doc * DOC_LEN + kt * 64 + r;
            *(float4*)&Ks[r][c] =
                *(const float4*)&k[(size_t)kg * D_MODEL + head * HEAD_DIM + c];
            *(float4*)&Vs[r][c] =
                *(const float4*)&v[(size_t)kg * D_MODEL + head * HEAD_DIM + c];
        }
        __syncthreads();

        for (int j = 0; j < 64; j++) {
            int tk = kt * 64 + j;
            int dlt = qi - tk;
            if (dlt < 0) dlt = -dlt;
            if (dlt < WIN) {
                float s = 0.f;
#pragma unroll
                for (int d = 0; d < HEAD_DIM; d++) s += qreg[d] * Ks[j][d];
                float mn = fmaxf(m, s);
                float corr = expf(m - mn);
                float p = expf(s - mn);
                l = l * corr + p;
#pragma unroll
                for (int d = 0; d < HEAD_DIM; d++)
                    o[d] = o[d] * corr + p * Vs[j][d];
                m = mn;
            }
        }
    }

    float invl = 1.f / l;
    size_t base = (size_t)qg * D_MODEL + head * HEAD_DIM;
#pragma unroll
    for (int d = 0; d < HEAD_DIM; d++) {
        __nv_bfloat16 h, lo;
        bsplit(o[d] * invl, h, lo);
        outH[base + d] = h;
        outL[base + d] = lo;
    }
}

// ---------------- SwiGLU -> split planes ----------------
__global__ __launch_bounds__(256)
void silu_mul_kernel(const float* __restrict__ f1, const float* __restrict__ f3,
                     __nv_bfloat16* __restrict__ oH,
                     __nv_bfloat16* __restrict__ oL, int n4) {
    int i = blockIdx.x * 256 + threadIdx.x;
    if (i < n4) {
        float4 a = ((const float4*)f1)[i];
        float4 b = ((const float4*)f3)[i];
        float r[4];
        r[0] = (a.x / (1.f + expf(-a.x))) * b.x;
        r[1] = (a.y / (1.f + expf(-a.y))) * b.y;
        r[2] = (a.z / (1.f + expf(-a.z))) * b.z;
        r[3] = (a.w / (1.f + expf(-a.w))) * b.w;
#pragma unroll
        for (int t = 0; t < 4; t++) {
            __nv_bfloat16 h, l;
            bsplit(r[t], h, l);
            oH[i * 4 + t] = h;
            oL[i * 4 + t] = l;
        }
    }
}

// ---------------- host orchestration ----------------
extern "C" void kernel_launch(void* const* d_in, const int* in_sizes, int n_in,
                              void* d_out, int out_size) {
    const float* x           = (const float*)d_in[0];
    const float* emb_w       = (const float*)d_in[1];
    const float* emb_b       = (const float*)d_in[2];
    const float* wq          = (const float*)d_in[3];
    const float* wk          = (const float*)d_in[4];
    const float* wv          = (const float*)d_in[5];
    const float* wo          = (const float*)d_in[6];
    const float* attn_norm_w = (const float*)d_in[7];
    const float* ffn_norm_w  = (const float*)d_in[8];
    const float* w1          = (const float*)d_in[9];
    const float* w2          = (const float*)d_in[10];
    const float* w3          = (const float*)d_in[11];
    const float* out_norm_w  = (const float*)d_in[12];
    const float* out_w       = (const float*)d_in[13];
    const int*   tok_id      = (const int*)d_in[15];
    float* out = (float*)d_out;

    float *h, *q, *k, *v, *f1, *f3;
    cudaGetSymbolAddress((void**)&h, g_h);
    cudaGetSymbolAddress((void**)&q, g_q);
    cudaGetSymbolAddress((void**)&k, g_k);
    cudaGetSymbolAddress((void**)&v, g_v);
    cudaGetSymbolAddress((void**)&f1, g_f1);
    cudaGetSymbolAddress((void**)&f3, g_f3);
    __nv_bfloat16 *wtH, *wtL, *xH, *xL, *hnH, *hnL, *attH, *attL, *f1H, *f1L;
    cudaGetSymbolAddress((void**)&wtH, g_wtH);
    cudaGetSymbolAddress((void**)&wtL, g_wtL);
    cudaGetSymbolAddress((void**)&xH, g_xH);
    cudaGetSymbolAddress((void**)&xL, g_xL);
    cudaGetSymbolAddress((void**)&hnH, g_hnH);
    cudaGetSymbolAddress((void**)&hnL, g_hnL);
    cudaGetSymbolAddress((void**)&attH, g_attH);
    cudaGetSymbolAddress((void**)&attL, g_attL);
    cudaGetSymbolAddress((void**)&f1H, g_f1H);
    cudaGetSymbolAddress((void**)&f1L, g_f1L);

    dim3 tb(32, 8);
    // weight prepass: transpose + split
    transpose_split<<<dim3(32, 32, 4), tb>>>(wq, wtH + OFF_WQ, wtL + OFF_WQ,
        D_MODEL, D_MODEL, (size_t)D_MODEL * D_MODEL, 1048576ULL);
    transpose_split<<<dim3(32, 32, 4), tb>>>(wk, wtH + OFF_WK, wtL + OFF_WK,
        D_MODEL, D_MODEL, (size_t)D_MODEL * D_MODEL, 1048576ULL);
    transpose_split<<<dim3(32, 32, 4), tb>>>(wv, wtH + OFF_WV, wtL + OFF_WV,
        D_MODEL, D_MODEL, (size_t)D_MODEL * D_MODEL, 1048576ULL);
    transpose_split<<<dim3(32, 32, 4), tb>>>(wo, wtH + OFF_WO, wtL + OFF_WO,
        D_MODEL, D_MODEL, (size_t)D_MODEL * D_MODEL, 1048576ULL);
    transpose_split<<<dim3(128, 32, 4), tb>>>(w1, wtH + OFF_W1, wtL + OFF_W1,
        D_MODEL, FFN_DIM, (size_t)D_MODEL * FFN_DIM, 4194304ULL);
    transpose_split<<<dim3(128, 32, 4), tb>>>(w3, wtH + OFF_W3, wtL + OFF_W3,
        D_MODEL, FFN_DIM, (size_t)D_MODEL * FFN_DIM, 4194304ULL);
    transpose_split<<<dim3(32, 128, 4), tb>>>(w2, wtH + OFF_W2, wtL + OFF_W2,
        FFN_DIM, D_MODEL, (size_t)FFN_DIM * D_MODEL, 4194304ULL);
    transpose_split<<<dim3(32, 2, 1), tb>>>(emb_w, wtH + OFF_EMB,
        wtL + OFF_EMB, IN_DIM, D_MODEL, 0ULL, 0ULL);
    transpose_split<<<dim3(4, 32, 1), tb>>>(out_w, wtH + OFF_OUT,
        wtL + OFF_OUT, D_MODEL, OUT_DIM, 0ULL, 0ULL);

    x_split_kernel<<<(S_LEN * IN_DIM + 255) / 256, 256>>>(x);

    // embed: h = x @ emb_w + emb_b
    tgemm_kernel<false, true><<<dim3(D_MODEL / 128, S_LEN / 128), 256>>>(
        xH, xL, wtH + OFF_EMB, wtL + OFF_EMB, emb_b, h,
        S_LEN, D_MODEL, IN_DIM);

    for (int l = 0; l < N_LAYERS; l++) {
        size_t oq = OFF_WQ + (size_t)l * 1048576;
        size_t ok = OFF_WK + (size_t)l * 1048576;
        size_t ov = OFF_WV + (size_t)l * 1048576;
        size_t oo = OFF_WO + (size_t)l * 1048576;
        size_t o1 = OFF_W1 + (size_t)l * 4194304;
        size_t o3 = OFF_W3 + (size_t)l * 4194304;
        size_t o2 = OFF_W2 + (size_t)l * 4194304;

        rmsnorm_split_kernel<<<S_LEN, 256>>>(h, attn_norm_w + l * D_MODEL,
                                             hnH, hnL);

        qkv_kernel<<<dim3(D_MODEL / 128, S_LEN / 128, 3), 256>>>(
            hnH, hnL, oq, ok, ov, q, k, v);

        rope_kernel<<<(S_LEN * N_HEADS * 32) / 256, 256>>>(q, k, tok_id);

        attention_kernel<<<dim3(N_DOCS, N_HEADS), 256>>>(q, k, v, attH, attL);

        tgemm_kernel<true, false><<<dim3(D_MODEL / 128, S_LEN / 128), 256>>>(
            attH, attL, wtH + oo, wtL + oo, nullptr, h,
            S_LEN, D_MODEL, D_MODEL);

        rmsnorm_split_kernel<<<S_LEN, 256>>>(h, ffn_norm_w + l * D_MODEL,
                                             hnH, hnL);

        w13_kernel<<<dim3(FFN_DIM / 128, S_LEN / 128, 2), 256>>>(
            hnH, hnL, o1, o3, f1, f3);

        silu_mul_kernel<<<(S_LEN * FFN_DIM / 4 + 255) / 256, 256>>>(
            f1, f3, f1H, f1L, S_LEN * FFN_DIM / 4);

        tgemm_kernel<true, false><<<dim3(D_MODEL / 128, S_LEN / 128), 256>>>(
            f1H, f1L, wtH + o2, wtL + o2, nullptr, h,
            S_LEN, D_MODEL, FFN_DIM);
    }

    rmsnorm_split_kernel<<<S_LEN, 256>>>(h, out_norm_w, hnH, hnL);
    tgemm_kernel<false, false><<<dim3(OUT_DIM / 128, S_LEN / 128), 256>>>(
        hnH, hnL, wtH + OFF_OUT, wtL + OFF_OUT, nullptr, out,
        S_LEN, OUT_DIM, D_MODEL);
}

// round 8
// speedup vs baseline: 1.5778x; 1.5739x over previous
#include <cuda_runtime.h>
#include <cuda_bf16.h>
#include <math.h>
#include <stdint.h>

#define S_LEN 2048
#define D_MODEL 1024
#define N_HEADS 16
#define HEAD_DIM 64
#define FFN_DIM 4096
#define N_LAYERS 4
#define IN_DIM 64
#define OUT_DIM 128
#define DOC_LEN 256
#define N_DOCS 8
#define WIN 128

// ---------------- fp32 scratch ----------------
__device__ float g_h [S_LEN * D_MODEL];
__device__ float g_q [S_LEN * D_MODEL];
__device__ float g_k [S_LEN * D_MODEL];
__device__ float g_v [S_LEN * D_MODEL];
__device__ float g_f1[S_LEN * FFN_DIM];
__device__ float g_f3[S_LEN * FFN_DIM];

// ---------------- bf16 split planes, K-tiled + SW128 pre-swizzled --------
// byte_addr(row,k,R) = ((k>>6)*(R>>3) + (row>>3))*1024 + swz((row&7)*128+(k&63)*2)
#define OFF_WQ  0ULL
#define OFF_WK  4194304ULL
#define OFF_WV  8388608ULL
#define OFF_WO  12582912ULL
#define OFF_W1  16777216ULL
#define OFF_W3  33554432ULL
#define OFF_W2  50331648ULL
#define OFF_EMB 67108864ULL
#define OFF_OUT 67174400ULL
#define WT_TOTAL 67305472ULL
__device__ __align__(1024) __nv_bfloat16 g_wtH[WT_TOTAL];
__device__ __align__(1024) __nv_bfloat16 g_wtL[WT_TOTAL];
__device__ __align__(1024) __nv_bfloat16 g_xH[S_LEN * IN_DIM];
__device__ __align__(1024) __nv_bfloat16 g_xL[S_LEN * IN_DIM];
__device__ __align__(1024) __nv_bfloat16 g_hnH[S_LEN * D_MODEL];
__device__ __align__(1024) __nv_bfloat16 g_hnL[S_LEN * D_MODEL];
__device__ __align__(1024) __nv_bfloat16 g_attH[S_LEN * D_MODEL];
__device__ __align__(1024) __nv_bfloat16 g_attL[S_LEN * D_MODEL];
__device__ __align__(1024) __nv_bfloat16 g_f1H[S_LEN * FFN_DIM];
__device__ __align__(1024) __nv_bfloat16 g_f1L[S_LEN * FFN_DIM];

__device__ __forceinline__ void bsplit(float x, __nv_bfloat16& h,
                                       __nv_bfloat16& l) {
    h = __float2bfloat16_rn(x);
    l = __float2bfloat16_rn(x - __bfloat162float(h));
}
__device__ __forceinline__ size_t kt_addr(int row, int k, int R) {
    uint32_t off = (uint32_t)((row & 7) * 128 + (k & 63) * 2);
    uint32_t sw = off ^ ((off >> 3) & 0x70);
    return ((size_t)(k >> 6) * (R >> 3) + (row >> 3)) * 1024 + sw;
}
#define MBAR_INIT(a, c) \
    asm volatile("mbarrier.init.shared.b64 [%0], %1;" :: "r"(a), "r"(c) : "memory")
#define MBAR_EXPECT_TX(a, b) \
    asm volatile("mbarrier.arrive.expect_tx.shared.b64 _, [%0], %1;" \
                 :: "r"(a), "r"(b) : "memory")
#define MBAR_WAIT(a, ph) do {                                                 \
    asm volatile("{\n\t.reg .pred P1;\n\tWL_%=:\n\t"                          \
        "mbarrier.try_wait.parity.acquire.cta.shared::cta.b64 P1, [%0], %1, 0x989680;\n\t" \
        "@P1 bra.uni WD_%=;\n\tbra.uni WL_%=;\n\tWD_%=:\n\t}"                 \
        :: "r"(a), "r"(ph) : "memory");                                       \
} while (0)
__device__ __forceinline__ void bulk_g2s(uint32_t dst, const void* src,
                                         uint32_t bytes, uint32_t mbar) {
    asm volatile(
        "cp.async.bulk.shared::cluster.global.mbarrier::complete_tx::bytes "
        "[%0], [%1], %2, [%3];"
        :: "r"(dst), "l"(src), "r"(bytes), "r"(mbar) : "memory");
}
__device__ __forceinline__ void mma_bf16(float* d, const uint32_t* a,
                                         const uint32_t* b) {
    asm volatile(
        "mma.sync.aligned.m16n8k16.row.col.f32.bf16.bf16.f32 "
        "{%0,%1,%2,%3}, {%4,%5,%6,%7}, {%8,%9}, {%0,%1,%2,%3};\n"
        : "+f"(d[0]), "+f"(d[1]), "+f"(d[2]), "+f"(d[3])
        : "r"(a[0]), "r"(a[1]), "r"(a[2]), "r"(a[3]), "r"(b[0]), "r"(b[1]));
}

// ============== bulk-copy + mma.sync GEMM ==============
// C[M,N] = A @ B^T; A planes [M][K] kt-layout, B planes [N][K] kt-layout.
// CTA 128x128x64-per-stage, 8 warps (2x4), warp 64x32, 3-term bf16 split.
// stage = A_H|A_L|B_H|B_L, 16KB each. 2 stages. Data at smem+1024.
#define STG_B 65536u

template <bool ADD, bool BIAS>
__device__ __forceinline__ void tc_core(
    const __nv_bfloat16* __restrict__ AH, const __nv_bfloat16* __restrict__ AL,
    const __nv_bfloat16* __restrict__ BH, const __nv_bfloat16* __restrict__ BL,
    const float* __restrict__ bias, float* __restrict__ C,
    int M, int N, int K) {
    extern __shared__ char smem[];
    const int tid = threadIdx.x;
    const int lane = tid & 31;
    const int w = tid >> 5;
    const int wm = w & 1;
    const int wn = w >> 1;
    const int rowBase = blockIdx.y * 128;
    const int colBase = blockIdx.x * 128;
    const int ac = lane & 3;
    const int lr = lane >> 2;

    uint32_t sb = (uint32_t)__cvta_generic_to_shared(smem);
    uint32_t mb_full[2] = { sb + 8, sb + 16 };

    if (tid == 0) {
        MBAR_INIT(mb_full[0], 1);
        MBAR_INIT(mb_full[1], 1);
        asm volatile("fence.proxy.async.shared::cta;" ::: "memory");
    }
    __syncthreads();

    const int S = K >> 6;

    auto load_stage = [&](int s) {
        uint32_t d = sb + 1024 + (uint32_t)(s & 1) * STG_B;
        uint32_t fb = mb_full[s & 1];
        size_t aoff = ((size_t)s * (M >> 3) + (rowBase >> 3)) * 1024;
        size_t boff = ((size_t)s * (N >> 3) + (colBase >> 3)) * 1024;
        MBAR_EXPECT_TX(fb, STG_B);
        bulk_g2s(d, (const char*)AH + aoff, 16384, fb);
        bulk_g2s(d + 16384, (const char*)AL + aoff, 16384, fb);
        bulk_g2s(d + 32768, (const char*)BH + boff, 16384, fb);
        bulk_g2s(d + 49152, (const char*)BL + boff, 16384, fb);
    };

    if (tid == 0) {
        load_stage(0);
        if (S > 1) load_stage(1);
    }

    float acc[4][4][4];
#pragma unroll
    for (int i = 0; i < 4; i++)
#pragma unroll
        for (int j = 0; j < 4; j++)
#pragma unroll
            for (int t = 0; t < 4; t++) acc[i][j][t] = 0.f;

    for (int s = 0; s < S; s++) {
        MBAR_WAIT(mb_full[s & 1], (s >> 1) & 1);
        const char* stg = smem + 1024 + (size_t)(s & 1) * STG_B;
        const char* pAH = stg;
        const char* pAL = stg + 16384;
        const char* pBH = stg + 32768;
        const char* pBL = stg + 49152;

#pragma unroll
        for (int c = 0; c < 4; c++) {           // k16 chunk
            uint32_t w1o = (uint32_t)(lr * 128 + c * 32 + ac * 4);
            uint32_t w2o = w1o + 16;
            uint32_t s1 = w1o ^ ((w1o >> 3) & 0x70);
            uint32_t s2 = w2o ^ ((w2o >> 3) & 0x70);

            uint32_t bh[4][2], bl[4][2];
#pragma unroll
            for (int j = 0; j < 4; j++) {
                uint32_t bb = (uint32_t)(wn * 4 + j) * 1024;
                bh[j][0] = *(const uint32_t*)(pBH + bb + s1);
                bh[j][1] = *(const uint32_t*)(pBH + bb + s2);
                bl[j][0] = *(const uint32_t*)(pBL + bb + s1);
                bl[j][1] = *(const uint32_t*)(pBL + bb + s2);
            }
#pragma unroll
            for (int i = 0; i < 4; i++) {
                uint32_t ab = (uint32_t)(wm * 8 + i * 2) * 1024;
                uint32_t ah[4], al[4];
                ah[0] = *(const uint32_t*)(pAH + ab + s1);
                ah[1] = *(const uint32_t*)(pAH + ab + 1024 + s1);
                ah[2] = *(const uint32_t*)(pAH + ab + s2);
                ah[3] = *(const uint32_t*)(pAH + ab + 1024 + s2);
                al[0] = *(const uint32_t*)(pAL + ab + s1);
                al[1] = *(const uint32_t*)(pAL + ab + 1024 + s1);
                al[2] = *(const uint32_t*)(pAL + ab + s2);
                al[3] = *(const uint32_t*)(pAL + ab + 1024 + s2);
#pragma unroll
                for (int j = 0; j < 4; j++) {
                    mma_bf16(acc[i][j], al, bh[j]);
                    mma_bf16(acc[i][j], ah, bl[j]);
                    mma_bf16(acc[i][j], ah, bh[j]);
                }
            }
        }
        __syncthreads();
        if (tid == 0 && s + 2 < S) load_stage(s + 2);
    }

    // epilogue (m16n8 acc: c0,c1 @ (lr, 2ac); c2,c3 @ (lr+8, 2ac))
#pragma unroll
    for (int i = 0; i < 4; i++) {
        int r0 = rowBase + wm * 64 + i * 16 + lr;
#pragma unroll
        for (int j = 0; j < 4; j++) {
            int c0 = colBase + wn * 32 + j * 8 + ac * 2;
            float2 v0 = make_float2(acc[i][j][0], acc[i][j][1]);
            float2 v1 = make_float2(acc[i][j][2], acc[i][j][3]);
            if (BIAS) {
                float b0 = bias[c0], b1 = bias[c0 + 1];
                v0.x += b0; v0.y += b1; v1.x += b0; v1.y += b1;
            }
            float* p0 = C + (size_t)r0 * N + c0;
            float* p1 = C + (size_t)(r0 + 8) * N + c0;
            if (ADD) {
                float2 o0 = *(float2*)p0, o1 = *(float2*)p1;
                v0.x += o0.x; v0.y += o0.y;
                v1.x += o1.x; v1.y += o1.y;
            }
            *(float2*)p0 = v0;
            *(float2*)p1 = v1;
        }
    }
}

template <bool ADD, bool BIAS>
__global__ __launch_bounds__(256)
void tg_kernel(const __nv_bfloat16* AH, const __nv_bfloat16* AL,
               const __nv_bfloat16* BH, const __nv_bfloat16* BL,
               const float* bias, float* C, int M, int N, int K) {
    tc_core<ADD, BIAS>(AH, AL, BH, BL, bias, C, M, N, K);
}

__global__ __launch_bounds__(256)
void qkv_kernel(const __nv_bfloat16* AH, const __nv_bfloat16* AL,
                size_t oq, size_t ok, size_t ov,
                float* q, float* k, float* v) {
    size_t off = (blockIdx.z == 0) ? oq : (blockIdx.z == 1) ? ok : ov;
    float* C = (blockIdx.z == 0) ? q : (blockIdx.z == 1) ? k : v;
    tc_core<false, false>(AH, AL, g_wtH + off, g_wtL + off, nullptr, C,
                          S_LEN, D_MODEL, D_MODEL);
}

__global__ __launch_bounds__(256)
void w13_kernel(const __nv_bfloat16* AH, const __nv_bfloat16* AL,
                size_t o1, size_t o3, float* f1, float* f3) {
    size_t off = (blockIdx.z == 0) ? o1 : o3;
    float* C = (blockIdx.z == 0) ? f1 : f3;
    tc_core<false, false>(AH, AL, g_wtH + off, g_wtL + off, nullptr, C,
                          S_LEN, FFN_DIM, D_MODEL);
}

// ---------------- weight transpose + split into kt layout ----------------
__global__ void transpose_split(const float* __restrict__ src,
                                __nv_bfloat16* __restrict__ dH,
                                __nv_bfloat16* __restrict__ dL,
                                int K, int N, size_t srcStride,
                                size_t dstStride) {
    src += (size_t)blockIdx.z * srcStride;
    dH += (size_t)blockIdx.z * dstStride;
    dL += (size_t)blockIdx.z * dstStride;
    __shared__ float t[32][33];
    int x = blockIdx.x * 32 + threadIdx.x;
    int y0 = blockIdx.y * 32;
#pragma unroll
    for (int i = 0; i < 32; i += 8)
        t[threadIdx.y + i][threadIdx.x] =
            src[(size_t)(y0 + threadIdx.y + i) * N + x];
    __syncthreads();
    int n = blockIdx.x * 32 + threadIdx.y;
    int kk = y0 + threadIdx.x;
#pragma unroll
    for (int i = 0; i < 32; i += 8) {
        float v = t[threadIdx.x][threadIdx.y + i];
        __nv_bfloat16 h, l;
        bsplit(v, h, l);
        size_t a = kt_addr(n + i, kk, N);
        *(__nv_bfloat16*)((char*)dH + a) = h;
        *(__nv_bfloat16*)((char*)dL + a) = l;
    }
}

__global__ __launch_bounds__(256)
void x_split_kernel(const float* __restrict__ x) {
    int i = blockIdx.x * 256 + threadIdx.x;
    if (i < S_LEN * IN_DIM) {
        __nv_bfloat16 h, l;
        bsplit(x[i], h, l);
        size_t a = kt_addr(i >> 6, i & 63, S_LEN);
        *(__nv_bfloat16*)((char*)g_xH + a) = h;
        *(__nv_bfloat16*)((char*)g_xL + a) = l;
    }
}

__global__ __launch_bounds__(256)
void rmsnorm_split_kernel(const float* __restrict__ x,
                          const float* __restrict__ w,
                          __nv_bfloat16* __restrict__ yH,
                          __nv_bfloat16* __restrict__ yL) {
    int row = blockIdx.x;
    const float* xr = x + (size_t)row * D_MODEL;
    float s = 0.f;
    for (int i = threadIdx.x; i < D_MODEL; i += 256) {
        float v = xr[i];
        s += v * v;
    }
    __shared__ float red[8];
#pragma unroll
    for (int o = 16; o; o >>= 1) s += __shfl_xor_sync(0xffffffffu, s, o);
    if ((threadIdx.x & 31) == 0) red[threadIdx.x >> 5] = s;
    __syncthreads();
    if (threadIdx.x < 8) {
        float t = red[threadIdx.x];
#pragma unroll
        for (int o = 4; o; o >>= 1) t += __shfl_xor_sync(0xffu, t, o);
        if (threadIdx.x == 0) red[0] = rsqrtf(t / (float)D_MODEL + 1e-5f);
    }
    __syncthreads();
    float r = red[0];
    for (int i = threadIdx.x; i < D_MODEL; i += 256) {
        float v = xr[i] * r * w[i];
        __nv_bfloat16 h, l;
        bsplit(v, h, l);
        size_t a = kt_addr(row, i, S_LEN);
        *(__nv_bfloat16*)((char*)yH + a) = h;
        *(__nv_bfloat16*)((char*)yL + a) = l;
    }
}

__global__ __launch_bounds__(256)
void rope_kernel(float* __restrict__ q, float* __restrict__ k,
                 const int* __restrict__ tok_id) {
    int idx = blockIdx.x * 256 + threadIdx.x;
    if (idx >= S_LEN * N_HEADS * (HEAD_DIM / 2)) return;
    int j = idx & 31;
    int h = (idx >> 5) & 15;
    int s = idx >> 9;
    float t = (float)tok_id[s];
    float inv = expf(-logf(10000.f) * (float)(2 * j) / (float)HEAD_DIM);
    float ang = t * inv;
    float c = cosf(ang), sn = sinf(ang);
    int base = s * D_MODEL + h * HEAD_DIM + j;
    float q1 = q[base], q2 = q[base + 32];
    q[base] = q1 * c - q2 * sn;
    q[base + 32] = q1 * sn + q2 * c;
    float k1 = k[base], k2 = k[base + 32];
    k[base] = k1 * c - k2 * sn;
    k[base + 32] = k1 * sn + k2 * c;
}

__global__ __launch_bounds__(256)
void attention_kernel(const float* __restrict__ q, const float* __restrict__ k,
                      const float* __restrict__ v,
                      __nv_bfloat16* __restrict__ outH,
                      __nv_bfloat16* __restrict__ outL) {
    const int doc = blockIdx.x;
    const int head = blockIdx.y;
    const int qi = threadIdx.x;
    const int qg = doc * DOC_LEN + qi;

    __shared__ float Ks[64][64];
    __shared__ float Vs[64][64];

    float qreg[HEAD_DIM];
    const float scale = 0.125f;
    const float* qp = q + (size_t)qg * D_MODEL + head * HEAD_DIM;
#pragma unroll
    for (int d = 0; d < HEAD_DIM; d += 4) {
        float4 t = *(const float4*)&qp[d];
        qreg[d] = t.x * scale; qreg[d + 1] = t.y * scale;
        qreg[d + 2] = t.z * scale; qreg[d + 3] = t.w * scale;
    }

    float o[HEAD_DIM];
#pragma unroll
    for (int d = 0; d < HEAD_DIM; d++) o[d] = 0.f;
    float m = -1e30f, l = 0.f;

    for (int kt = 0; kt < 4; kt++) {
        __syncthreads();
        for (int f = threadIdx.x; f < 1024; f += 256) {
            int r = f >> 4;
            int c = (f & 15) << 2;
            int kg = doc * DOC_LEN + kt * 64 + r;
            *(float4*)&Ks[r][c] =
                *(const float4*)&k[(size_t)kg * D_MODEL + head * HEAD_DIM + c];
            *(float4*)&Vs[r][c] =
                *(const float4*)&v[(size_t)kg * D_MODEL + head * HEAD_DIM + c];
        }
        __syncthreads();

        for (int j = 0; j < 64; j++) {
            int tk = kt * 64 + j;
            int dlt = qi - tk;
            if (dlt < 0) dlt = -dlt;
            if (dlt < WIN) {
                float s = 0.f;
#pragma unroll
                for (int d = 0; d < HEAD_DIM; d++) s += qreg[d] * Ks[j][d];
                float mn = fmaxf(m, s);
                float corr = expf(m - mn);
                float p = expf(s - mn);
                l = l * corr + p;
#pragma unroll
                for (int d = 0; d < HEAD_DIM; d++)
                    o[d] = o[d] * corr + p * Vs[j][d];
                m = mn;
            }
        }
    }

    float invl = 1.f / l;
#pragma unroll
    for (int d = 0; d < HEAD_DIM; d++) {
        __nv_bfloat16 h, lo;
        bsplit(o[d] * invl, h, lo);
        size_t a = kt_addr(qg, head * HEAD_DIM + d, S_LEN);
        *(__nv_bfloat16*)((char*)outH + a) = h;
        *(__nv_bfloat16*)((char*)outL + a) = lo;
    }
}

__global__ __launch_bounds__(256)
void silu_mul_kernel(const float* __restrict__ f1, const float* __restrict__ f3,
                     __nv_bfloat16* __restrict__ oH,
                     __nv_bfloat16* __restrict__ oL, int n4) {
    int i = blockIdx.x * 256 + threadIdx.x;
    if (i < n4) {
        float4 a = ((const float4*)f1)[i];
        float4 b = ((const float4*)f3)[i];
        float r[4];
        r[0] = (a.x / (1.f + expf(-a.x))) * b.x;
        r[1] = (a.y / (1.f + expf(-a.y))) * b.y;
        r[2] = (a.z / (1.f + expf(-a.z))) * b.z;
        r[3] = (a.w / (1.f + expf(-a.w))) * b.w;
#pragma unroll
        for (int t = 0; t < 4; t++) {
            int e = i * 4 + t;
            __nv_bfloat16 h, l;
            bsplit(r[t], h, l);
            size_t adr = kt_addr(e >> 12, e & 4095, S_LEN);
            *(__nv_bfloat16*)((char*)oH + adr) = h;
            *(__nv_bfloat16*)((char*)oL + adr) = l;
        }
    }
}

// ---------------- host orchestration ----------------
extern "C" void kernel_launch(void* const* d_in, const int* in_sizes, int n_in,
                              void* d_out, int out_size) {
    const float* x           = (const float*)d_in[0];
    const float* emb_w       = (const float*)d_in[1];
    const float* emb_b       = (const float*)d_in[2];
    const float* wq          = (const float*)d_in[3];
    const float* wk          = (const float*)d_in[4];
    const float* wv          = (const float*)d_in[5];
    const float* wo          = (const float*)d_in[6];
    const float* attn_norm_w = (const float*)d_in[7];
    const float* ffn_norm_w  = (const float*)d_in[8];
    const float* w1          = (const float*)d_in[9];
    const float* w2          = (const float*)d_in[10];
    const float* w3          = (const float*)d_in[11];
    const float* out_norm_w  = (const float*)d_in[12];
    const float* out_w       = (const float*)d_in[13];
    const int*   tok_id      = (const int*)d_in[15];
    float* out = (float*)d_out;

    float *h, *q, *k, *v, *f1, *f3;
    cudaGetSymbolAddress((void**)&h, g_h);
    cudaGetSymbolAddress((void**)&q, g_q);
    cudaGetSymbolAddress((void**)&k, g_k);
    cudaGetSymbolAddress((void**)&v, g_v);
    cudaGetSymbolAddress((void**)&f1, g_f1);
    cudaGetSymbolAddress((void**)&f3, g_f3);
    __nv_bfloat16 *wtH, *wtL, *xH, *xL, *hnH, *hnL, *attH, *attL, *f1H, *f1L;
    cudaGetSymbolAddress((void**)&wtH, g_wtH);
    cudaGetSymbolAddress((void**)&wtL, g_wtL);
    cudaGetSymbolAddress((void**)&xH, g_xH);
    cudaGetSymbolAddress((void**)&xL, g_xL);
    cudaGetSymbolAddress((void**)&hnH, g_hnH);
    cudaGetSymbolAddress((void**)&hnL, g_hnL);
    cudaGetSymbolAddress((void**)&attH, g_attH);
    cudaGetSymbolAddress((void**)&attL, g_attL);
    cudaGetSymbolAddress((void**)&f1H, g_f1H);
    cudaGetSymbolAddress((void**)&f1L, g_f1L);

    const int SMT = 1024 + 2 * 65536;    // 132096
    cudaFuncSetAttribute(tg_kernel<false, true>,
                         cudaFuncAttributeMaxDynamicSharedMemorySize, SMT);
    cudaFuncSetAttribute(tg_kernel<true, false>,
                         cudaFuncAttributeMaxDynamicSharedMemorySize, SMT);
    cudaFuncSetAttribute(tg_kernel<false, false>,
                         cudaFuncAttributeMaxDynamicSharedMemorySize, SMT);
    cudaFuncSetAttribute(qkv_kernel,
                         cudaFuncAttributeMaxDynamicSharedMemorySize, SMT);
    cudaFuncSetAttribute(w13_kernel,
                         cudaFuncAttributeMaxDynamicSharedMemorySize, SMT);

    dim3 tb(32, 8);
    transpose_split<<<dim3(32, 32, 4), tb>>>(wq, wtH + OFF_WQ, wtL + OFF_WQ,
        D_MODEL, D_MODEL, (size_t)D_MODEL * D_MODEL, 1048576ULL);
    transpose_split<<<dim3(32, 32, 4), tb>>>(wk, wtH + OFF_WK, wtL + OFF_WK,
        D_MODEL, D_MODEL, (size_t)D_MODEL * D_MODEL, 1048576ULL);
    transpose_split<<<dim3(32, 32, 4), tb>>>(wv, wtH + OFF_WV, wtL + OFF_WV,
        D_MODEL, D_MODEL, (size_t)D_MODEL * D_MODEL, 1048576ULL);
    transpose_split<<<dim3(32, 32, 4), tb>>>(wo, wtH + OFF_WO, wtL + OFF_WO,
        D_MODEL, D_MODEL, (size_t)D_MODEL * D_MODEL, 1048576ULL);
    transpose_split<<<dim3(128, 32, 4), tb>>>(w1, wtH + OFF_W1, wtL + OFF_W1,
        D_MODEL, FFN_DIM, (size_t)D_MODEL * FFN_DIM, 4194304ULL);
    transpose_split<<<dim3(128, 32, 4), tb>>>(w3, wtH + OFF_W3, wtL + OFF_W3,
        D_MODEL, FFN_DIM, (size_t)D_MODEL * FFN_DIM, 4194304ULL);
    transpose_split<<<dim3(32, 128, 4), tb>>>(w2, wtH + OFF_W2, wtL + OFF_W2,
        FFN_DIM, D_MODEL, (size_t)FFN_DIM * D_MODEL, 4194304ULL);
    transpose_split<<<dim3(32, 2, 1), tb>>>(emb_w, wtH + OFF_EMB,
        wtL + OFF_EMB, IN_DIM, D_MODEL, 0ULL, 0ULL);
    transpose_split<<<dim3(4, 32, 1), tb>>>(out_w, wtH + OFF_OUT,
        wtL + OFF_OUT, D_MODEL, OUT_DIM, 0ULL, 0ULL);

    x_split_kernel<<<(S_LEN * IN_DIM + 255) / 256, 256>>>(x);

    // embed: h = x @ emb_w + emb_b   (K=64 -> single stage)
    tg_kernel<false, true><<<dim3(8, 16), 256, SMT>>>(
        xH, xL, wtH + OFF_EMB, wtL + OFF_EMB, emb_b, h,
        S_LEN, D_MODEL, IN_DIM);

    for (int l = 0; l < N_LAYERS; l++) {
        size_t oq = OFF_WQ + (size_t)l * 1048576;
        size_t ok = OFF_WK + (size_t)l * 1048576;
        size_t ov = OFF_WV + (size_t)l * 1048576;
        size_t oo = OFF_WO + (size_t)l * 1048576;
        size_t o1 = OFF_W1 + (size_t)l * 4194304;
        size_t o3 = OFF_W3 + (size_t)l * 4194304;
        size_t o2 = OFF_W2 + (size_t)l * 4194304;

        rmsnorm_split_kernel<<<S_LEN, 256>>>(h, attn_norm_w + l * D_MODEL,
                                             hnH, hnL);

        qkv_kernel<<<dim3(8, 16, 3), 256, SMT>>>(hnH, hnL, oq, ok, ov,
                                                 q, k, v);

        rope_kernel<<<(S_LEN * N_HEADS * 32) / 256, 256>>>(q, k, tok_id);

        attention_kernel<<<dim3(N_DOCS, N_HEADS), 256>>>(q, k, v, attH, attL);

        tg_kernel<true, false><<<dim3(8, 16), 256, SMT>>>(
            attH, attL, wtH + oo, wtL + oo, nullptr, h,
            S_LEN, D_MODEL, D_MODEL);

        rmsnorm_split_kernel<<<S_LEN, 256>>>(h, ffn_norm_w + l * D_MODEL,
                                             hnH, hnL);

        w13_kernel<<<dim3(32, 16, 2), 256, SMT>>>(hnH, hnL, o1, o3, f1, f3);

        silu_mul_kernel<<<(S_LEN * FFN_DIM / 4 + 255) / 256, 256>>>(
            f1, f3, f1H, f1L, S_LEN * FFN_DIM / 4);

        tg_kernel<true, false><<<dim3(8, 16), 256, SMT>>>(
            f1H, f1L, wtH + o2, wtL + o2, nullptr, h,
            S_LEN, D_MODEL, FFN_DIM);
    }

    rmsnorm_split_kernel<<<S_LEN, 256>>>(h, out_norm_w, hnH, hnL);
    tg_kernel<false, false><<<dim3(1, 16), 256, SMT>>>(
        hnH, hnL, wtH + OFF_OUT, wtL + OFF_OUT, nullptr, out,
        S_LEN, OUT_DIM, D_MODEL);
}

// round 9
// speedup vs baseline: 1.5847x; 1.0044x over previous
#include <cuda_runtime.h>
#include <cuda_bf16.h>
#include <math.h>
#include <stdint.h>

#define S_LEN 2048
#define D_MODEL 1024
#define N_HEADS 16
#define HEAD_DIM 64
#define FFN_DIM 4096
#define N_LAYERS 4
#define IN_DIM 64
#define OUT_DIM 128
#define DOC_LEN 256
#define N_DOCS 8
#define WIN 128

// ---------------- fp32 scratch ----------------
__device__ float g_h [S_LEN * D_MODEL];
__device__ float g_q [S_LEN * D_MODEL];
__device__ float g_k [S_LEN * D_MODEL];
__device__ float g_v [S_LEN * D_MODEL];
__device__ float g_f1[S_LEN * FFN_DIM];
__device__ float g_f3[S_LEN * FFN_DIM];

// ---------------- bf16 split planes, K-tiled + SW128 pre-swizzled --------
// byte_addr(row,k,R) = ((k>>6)*(R>>3) + (row>>3))*1024 + swz((row&7)*128+(k&63)*2)
#define OFF_WQ  0ULL
#define OFF_WK  4194304ULL
#define OFF_WV  8388608ULL
#define OFF_WO  12582912ULL
#define OFF_W1  16777216ULL
#define OFF_W3  33554432ULL
#define OFF_W2  50331648ULL
#define OFF_EMB 67108864ULL
#define OFF_OUT 67174400ULL
#define WT_TOTAL 67305472ULL
__device__ __align__(1024) __nv_bfloat16 g_wtH[WT_TOTAL];
__device__ __align__(1024) __nv_bfloat16 g_wtL[WT_TOTAL];
__device__ __align__(1024) __nv_bfloat16 g_xH[S_LEN * IN_DIM];
__device__ __align__(1024) __nv_bfloat16 g_xL[S_LEN * IN_DIM];
__device__ __align__(1024) __nv_bfloat16 g_hnH[S_LEN * D_MODEL];
__device__ __align__(1024) __nv_bfloat16 g_hnL[S_LEN * D_MODEL];
__device__ __align__(1024) __nv_bfloat16 g_attH[S_LEN * D_MODEL];
__device__ __align__(1024) __nv_bfloat16 g_attL[S_LEN * D_MODEL];
__device__ __align__(1024) __nv_bfloat16 g_f1H[S_LEN * FFN_DIM];
__device__ __align__(1024) __nv_bfloat16 g_f1L[S_LEN * FFN_DIM];

__device__ __forceinline__ void bsplit(float x, __nv_bfloat16& h,
                                       __nv_bfloat16& l) {
    h = __float2bfloat16_rn(x);
    l = __float2bfloat16_rn(x - __bfloat162float(h));
}
__device__ __forceinline__ size_t kt_addr(int row, int k, int R) {
    uint32_t off = (uint32_t)((row & 7) * 128 + (k & 63) * 2);
    uint32_t sw = off ^ ((off >> 3) & 0x70);
    return ((size_t)(k >> 6) * (R >> 3) + (row >> 3)) * 1024 + sw;
}
#define MBAR_INIT(a, c) \
    asm volatile("mbarrier.init.shared.b64 [%0], %1;" :: "r"(a), "r"(c) : "memory")
#define MBAR_EXPECT_TX(a, b) \
    asm volatile("mbarrier.arrive.expect_tx.shared.b64 _, [%0], %1;" \
                 :: "r"(a), "r"(b) : "memory")
#define MBAR_WAIT(a, ph) do {                                                 \
    asm volatile("{\n\t.reg .pred P1;\n\tWL_%=:\n\t"                          \
        "mbarrier.try_wait.parity.acquire.cta.shared::cta.b64 P1, [%0], %1, 0x989680;\n\t" \
        "@P1 bra.uni WD_%=;\n\tbra.uni WL_%=;\n\tWD_%=:\n\t}"                 \
        :: "r"(a), "r"(ph) : "memory");                                       \
} while (0)
__device__ __forceinline__ void bulk_g2s(uint32_t dst, const void* src,
                                         uint32_t bytes, uint32_t mbar) {
    asm volatile(
        "cp.async.bulk.shared::cluster.global.mbarrier::complete_tx::bytes "
        "[%0], [%1], %2, [%3];"
        :: "r"(dst), "l"(src), "r"(bytes), "r"(mbar) : "memory");
}
__device__ __forceinline__ void mma_bf16(float* d, const uint32_t* a,
                                         const uint32_t* b) {
    asm volatile(
        "mma.sync.aligned.m16n8k16.row.col.f32.bf16.bf16.f32 "
        "{%0,%1,%2,%3}, {%4,%5,%6,%7}, {%8,%9}, {%0,%1,%2,%3};\n"
        : "+f"(d[0]), "+f"(d[1]), "+f"(d[2]), "+f"(d[3])
        : "r"(a[0]), "r"(a[1]), "r"(a[2]), "r"(a[3]), "r"(b[0]), "r"(b[1]));
}
__device__ __forceinline__ void ldsm4(uint32_t* r, uint32_t addr) {
    asm volatile(
        "ldmatrix.sync.aligned.m8n8.x4.shared.b16 {%0,%1,%2,%3}, [%4];"
        : "=r"(r[0]), "=r"(r[1]), "=r"(r[2]), "=r"(r[3]) : "r"(addr));
}

// ============== bulk-copy + ldmatrix + mma.sync GEMM ==============
// C[M,N] = A @ B^T; A planes [M][K] kt-layout, B planes [N][K] kt-layout.
// CTA 128x128x64-per-stage, 8 warps (2x4), warp 64x32, 3-term bf16 split.
// stage = A_H|A_L|B_H|B_L, 16KB each. 3 stages. Data at smem+1024.
#define STG_B 65536u
#define N_STG 3

template <bool ADD, bool BIAS>
__device__ __forceinline__ void tc_core(
    const __nv_bfloat16* __restrict__ AH, const __nv_bfloat16* __restrict__ AL,
    const __nv_bfloat16* __restrict__ BH, const __nv_bfloat16* __restrict__ BL,
    const float* __restrict__ bias, float* __restrict__ C,
    int M, int N, int K) {
    extern __shared__ char smem[];
    const int tid = threadIdx.x;
    const int lane = tid & 31;
    const int w = tid >> 5;
    const int wm = w & 1;
    const int wn = w >> 1;
    const int rowBase = blockIdx.y * 128;
    const int colBase = blockIdx.x * 128;
    const int ac = lane & 3;
    const int lr = lane >> 2;

    uint32_t sb = (uint32_t)__cvta_generic_to_shared(smem);
    uint32_t mb_full[N_STG] = { sb + 8, sb + 16, sb + 24 };

    if (tid == 0) {
        MBAR_INIT(mb_full[0], 1);
        MBAR_INIT(mb_full[1], 1);
        MBAR_INIT(mb_full[2], 1);
        asm volatile("fence.proxy.async.shared::cta;" ::: "memory");
    }
    __syncthreads();

    const int S = K >> 6;

    auto load_stage = [&](int s) {
        uint32_t d = sb + 1024 + (uint32_t)(s % N_STG) * STG_B;
        uint32_t fb = mb_full[s % N_STG];
        size_t aoff = ((size_t)s * (M >> 3) + (rowBase >> 3)) * 1024;
        size_t boff = ((size_t)s * (N >> 3) + (colBase >> 3)) * 1024;
        MBAR_EXPECT_TX(fb, STG_B);
        bulk_g2s(d, (const char*)AH + aoff, 16384, fb);
        bulk_g2s(d + 16384, (const char*)AL + aoff, 16384, fb);
        bulk_g2s(d + 32768, (const char*)BH + boff, 16384, fb);
        bulk_g2s(d + 49152, (const char*)BL + boff, 16384, fb);
    };

    if (tid == 0) {
        load_stage(0);
        if (S > 1) load_stage(1);
        if (S > 2) load_stage(2);
    }

    // ldmatrix per-thread address offsets (within a plane, per k16 chunk c)
    const int lm = lane >> 3;     // matrix index group
    const int rr = lane & 7;
    uint32_t aoffc[4], boffc[4];
#pragma unroll
    for (int c = 0; c < 4; c++) {
        uint32_t ao = (uint32_t)(rr * 128 + c * 32 + (lm >> 1) * 16);
        aoffc[c] = (uint32_t)((lm & 1) * 1024) + (ao ^ ((ao >> 3) & 0x70));
        uint32_t bo = (uint32_t)(rr * 128 + c * 32 + (lm & 1) * 16);
        boffc[c] = (uint32_t)((lm >> 1) * 1024) + (bo ^ ((bo >> 3) & 0x70));
    }

    float acc[4][4][4];
#pragma unroll
    for (int i = 0; i < 4; i++)
#pragma unroll
        for (int j = 0; j < 4; j++)
#pragma unroll
            for (int t = 0; t < 4; t++) acc[i][j][t] = 0.f;

    for (int s = 0; s < S; s++) {
        MBAR_WAIT(mb_full[s % N_STG], (s / N_STG) & 1);
        uint32_t stg = sb + 1024 + (uint32_t)(s % N_STG) * STG_B;
        uint32_t pAH = stg;
        uint32_t pAL = stg + 16384;
        uint32_t pBH = stg + 32768;
        uint32_t pBL = stg + 49152;
        uint32_t bB = (uint32_t)(wn * 4) * 1024;

#pragma unroll
        for (int c = 0; c < 4; c++) {           // k16 chunk
            uint32_t bh[8], bl[8];              // [2*j], [2*j+1]
            ldsm4(bh,     pBH + bB + boffc[c]);
            ldsm4(bh + 4, pBH + bB + 2048 + boffc[c]);
            ldsm4(bl,     pBL + bB + boffc[c]);
            ldsm4(bl + 4, pBL + bB + 2048 + boffc[c]);
#pragma unroll
            for (int i = 0; i < 4; i++) {
                uint32_t aB = (uint32_t)(wm * 8 + i * 2) * 1024;
                uint32_t ah[4], al[4];
                ldsm4(ah, pAH + aB + aoffc[c]);
                ldsm4(al, pAL + aB + aoffc[c]);
#pragma unroll
                for (int j = 0; j < 4; j++) {
                    mma_bf16(acc[i][j], al, bh + 2 * j);
                    mma_bf16(acc[i][j], ah, bl + 2 * j);
                    mma_bf16(acc[i][j], ah, bh + 2 * j);
                }
            }
        }
        __syncthreads();
        if (tid == 0 && s + N_STG < S) load_stage(s + N_STG);
    }

    // epilogue (m16n8 acc: c0,c1 @ (lr, 2ac); c2,c3 @ (lr+8, 2ac))
#pragma unroll
    for (int i = 0; i < 4; i++) {
        int r0 = rowBase + wm * 64 + i * 16 + lr;
#pragma unroll
        for (int j = 0; j < 4; j++) {
            int c0 = colBase + wn * 32 + j * 8 + ac * 2;
            float2 v0 = make_float2(acc[i][j][0], acc[i][j][1]);
            float2 v1 = make_float2(acc[i][j][2], acc[i][j][3]);
            if (BIAS) {
                float b0 = bias[c0], b1 = bias[c0 + 1];
                v0.x += b0; v0.y += b1; v1.x += b0; v1.y += b1;
            }
            float* p0 = C + (size_t)r0 * N + c0;
            float* p1 = C + (size_t)(r0 + 8) * N + c0;
            if (ADD) {
                float2 o0 = *(float2*)p0, o1 = *(float2*)p1;
                v0.x += o0.x; v0.y += o0.y;
                v1.x += o1.x; v1.y += o1.y;
            }
            *(float2*)p0 = v0;
            *(float2*)p1 = v1;
        }
    }
}

template <bool ADD, bool BIAS>
__global__ __launch_bounds__(256)
void tg_kernel(const __nv_bfloat16* AH, const __nv_bfloat16* AL,
               const __nv_bfloat16* BH, const __nv_bfloat16* BL,
               const float* bias, float* C, int M, int N, int K) {
    tc_core<ADD, BIAS>(AH, AL, BH, BL, bias, C, M, N, K);
}

__global__ __launch_bounds__(256)
void qkv_kernel(const __nv_bfloat16* AH, const __nv_bfloat16* AL,
                size_t oq, size_t ok, size_t ov,
                float* q, float* k, float* v) {
    size_t off = (blockIdx.z == 0) ? oq : (blockIdx.z == 1) ? ok : ov;
    float* C = (blockIdx.z == 0) ? q : (blockIdx.z == 1) ? k : v;
    tc_core<false, false>(AH, AL, g_wtH + off, g_wtL + off, nullptr, C,
                          S_LEN, D_MODEL, D_MODEL);
}

__global__ __launch_bounds__(256)
void w13_kernel(const __nv_bfloat16* AH, const __nv_bfloat16* AL,
                size_t o1, size_t o3, float* f1, float* f3) {
    size_t off = (blockIdx.z == 0) ? o1 : o3;
    float* C = (blockIdx.z == 0) ? f1 : f3;
    tc_core<false, false>(AH, AL, g_wtH + off, g_wtL + off, nullptr, C,
                          S_LEN, FFN_DIM, D_MODEL);
}

// ---------------- weight transpose + split into kt layout ----------------
__global__ void transpose_split(const float* __restrict__ src,
                                __nv_bfloat16* __restrict__ dH,
                                __nv_bfloat16* __restrict__ dL,
                                int K, int N, size_t srcStride,
                                size_t dstStride) {
    src += (size_t)blockIdx.z * srcStride;
    dH += (size_t)blockIdx.z * dstStride;
    dL += (size_t)blockIdx.z * dstStride;
    __shared__ float t[32][33];
    int x = blockIdx.x * 32 + threadIdx.x;
    int y0 = blockIdx.y * 32;
#pragma unroll
    for (int i = 0; i < 32; i += 8)
        t[threadIdx.y + i][threadIdx.x] =
            src[(size_t)(y0 + threadIdx.y + i) * N + x];
    __syncthreads();
    int n = blockIdx.x * 32 + threadIdx.y;
    int kk = y0 + threadIdx.x;
#pragma unroll
    for (int i = 0; i < 32; i += 8) {
        float v = t[threadIdx.x][threadIdx.y + i];
        __nv_bfloat16 h, l;
        bsplit(v, h, l);
        size_t a = kt_addr(n + i, kk, N);
        *(__nv_bfloat16*)((char*)dH + a) = h;
        *(__nv_bfloat16*)((char*)dL + a) = l;
    }
}

__global__ __launch_bounds__(256)
void x_split_kernel(const float* __restrict__ x) {
    int i = blockIdx.x * 256 + threadIdx.x;
    if (i < S_LEN * IN_DIM) {
        __nv_bfloat16 h, l;
        bsplit(x[i], h, l);
        size_t a = kt_addr(i >> 6, i & 63, S_LEN);
        *(__nv_bfloat16*)((char*)g_xH + a) = h;
        *(__nv_bfloat16*)((char*)g_xL + a) = l;
    }
}

__global__ __launch_bounds__(256)
void rmsnorm_split_kernel(const float* __restrict__ x,
                          const float* __restrict__ w,
                          __nv_bfloat16* __restrict__ yH,
                          __nv_bfloat16* __restrict__ yL) {
    int row = blockIdx.x;
    const float* xr = x + (size_t)row * D_MODEL;
    float s = 0.f;
    for (int i = threadIdx.x; i < D_MODEL; i += 256) {
        float v = xr[i];
        s += v * v;
    }
    __shared__ float red[8];
#pragma unroll
    for (int o = 16; o; o >>= 1) s += __shfl_xor_sync(0xffffffffu, s, o);
    if ((threadIdx.x & 31) == 0) red[threadIdx.x >> 5] = s;
    __syncthreads();
    if (threadIdx.x < 8) {
        float t = red[threadIdx.x];
#pragma unroll
        for (int o = 4; o; o >>= 1) t += __shfl_xor_sync(0xffu, t, o);
        if (threadIdx.x == 0) red[0] = rsqrtf(t / (float)D_MODEL + 1e-5f);
    }
    __syncthreads();
    float r = red[0];
    for (int i = threadIdx.x; i < D_MODEL; i += 256) {
        float v = xr[i] * r * w[i];
        __nv_bfloat16 h, l;
        bsplit(v, h, l);
        size_t a = kt_addr(row, i, S_LEN);
        *(__nv_bfloat16*)((char*)yH + a) = h;
        *(__nv_bfloat16*)((char*)yL + a) = l;
    }
}

__global__ __launch_bounds__(256)
void rope_kernel(float* __restrict__ q, float* __restrict__ k,
                 const int* __restrict__ tok_id) {
    int idx = blockIdx.x * 256 + threadIdx.x;
    if (idx >= S_LEN * N_HEADS * (HEAD_DIM / 2)) return;
    int j = idx & 31;
    int h = (idx >> 5) & 15;
    int s = idx >> 9;
    float t = (float)tok_id[s];
    float inv = expf(-logf(10000.f) * (float)(2 * j) / (float)HEAD_DIM);
    float ang = t * inv;
    float c = cosf(ang), sn = sinf(ang);
    int base = s * D_MODEL + h * HEAD_DIM + j;
    float q1 = q[base], q2 = q[base + 32];
    q[base] = q1 * c - q2 * sn;
    q[base + 32] = q1 * sn + q2 * c;
    float k1 = k[base], k2 = k[base + 32];
    k[base] = k1 * c - k2 * sn;
    k[base + 32] = k1 * sn + k2 * c;
}

__global__ __launch_bounds__(256)
void attention_kernel(const float* __restrict__ q, const float* __restrict__ k,
                      const float* __restrict__ v,
                      __nv_bfloat16* __restrict__ outH,
                      __nv_bfloat16* __restrict__ outL) {
    const int doc = blockIdx.x;
    const int head = blockIdx.y;
    const int qi = threadIdx.x;
    const int qg = doc * DOC_LEN + qi;

    __shared__ float Ks[64][64];
    __shared__ float Vs[64][64];

    float qreg[HEAD_DIM];
    const float scale = 0.125f;
    const float* qp = q + (size_t)qg * D_MODEL + head * HEAD_DIM;
#pragma unroll
    for (int d = 0; d < HEAD_DIM; d += 4) {
        float4 t = *(const float4*)&qp[d];
        qreg[d] = t.x * scale; qreg[d + 1] = t.y * scale;
        qreg[d + 2] = t.z * scale; qreg[d + 3] = t.w * scale;
    }

    float o[HEAD_DIM];
#pragma unroll
    for (int d = 0; d < HEAD_DIM; d++) o[d] = 0.f;
    float m = -1e30f, l = 0.f;

    for (int kt = 0; kt < 4; kt++) {
        __syncthreads();
        for (int f = threadIdx.x; f < 1024; f += 256) {
            int r = f >> 4;
            int c = (f & 15) << 2;
            int kg = doc * DOC_LEN + kt * 64 + r;
            *(float4*)&Ks[r][c] =
                *(const float4*)&k[(size_t)kg * D_MODEL + head * HEAD_DIM + c];
            *(float4*)&Vs[r][c] =
                *(const float4*)&v[(size_t)kg * D_MODEL + head * HEAD_DIM + c];
        }
        __syncthreads();

        for (int j = 0; j < 64; j++) {
            int tk = kt * 64 + j;
            int dlt = qi - tk;
            if (dlt < 0) dlt = -dlt;
            if (dlt < WIN) {
                float s = 0.f;
#pragma unroll
                for (int d = 0; d < HEAD_DIM; d++) s += qreg[d] * Ks[j][d];
                float mn = fmaxf(m, s);
                float corr = expf(m - mn);
                float p = expf(s - mn);
                l = l * corr + p;
#pragma unroll
                for (int d = 0; d < HEAD_DIM; d++)
                    o[d] = o[d] * corr + p * Vs[j][d];
                m = mn;
            }
        }
    }

    float invl = 1.f / l;
#pragma unroll
    for (int d = 0; d < HEAD_DIM; d++) {
        __nv_bfloat16 h, lo;
        bsplit(o[d] * invl, h, lo);
        size_t a = kt_addr(qg, head * HEAD_DIM + d, S_LEN);
        *(__nv_bfloat16*)((char*)outH + a) = h;
        *(__nv_bfloat16*)((char*)outL + a) = lo;
    }
}

__global__ __launch_bounds__(256)
void silu_mul_kernel(const float* __restrict__ f1, const float* __restrict__ f3,
                     __nv_bfloat16* __restrict__ oH,
                     __nv_bfloat16* __restrict__ oL, int n4) {
    int i = blockIdx.x * 256 + threadIdx.x;
    if (i < n4) {
        float4 a = ((const float4*)f1)[i];
        float4 b = ((const float4*)f3)[i];
        float r[4];
        r[0] = (a.x / (1.f + expf(-a.x))) * b.x;
        r[1] = (a.y / (1.f + expf(-a.y))) * b.y;
        r[2] = (a.z / (1.f + expf(-a.z))) * b.z;
        r[3] = (a.w / (1.f + expf(-a.w))) * b.w;
#pragma unroll
        for (int t = 0; t < 4; t++) {
            int e = i * 4 + t;
            __nv_bfloat16 h, l;
            bsplit(r[t], h, l);
            size_t adr = kt_addr(e >> 12, e & 4095, S_LEN);
            *(__nv_bfloat16*)((char*)oH + adr) = h;
            *(__nv_bfloat16*)((char*)oL + adr) = l;
        }
    }
}

// ---------------- host orchestration ----------------
extern "C" void kernel_launch(void* const* d_in, const int* in_sizes, int n_in,
                              void* d_out, int out_size) {
    const float* x           = (const float*)d_in[0];
    const float* emb_w       = (const float*)d_in[1];
    const float* emb_b       = (const float*)d_in[2];
    const float* wq          = (const float*)d_in[3];
    const float* wk          = (const float*)d_in[4];
    const float* wv          = (const float*)d_in[5];
    const float* wo          = (const float*)d_in[6];
    const float* attn_norm_w = (const float*)d_in[7];
    const float* ffn_norm_w  = (const float*)d_in[8];
    const float* w1          = (const float*)d_in[9];
    const float* w2          = (const float*)d_in[10];
    const float* w3          = (const float*)d_in[11];
    const float* out_norm_w  = (const float*)d_in[12];
    const float* out_w       = (const float*)d_in[13];
    const int*   tok_id      = (const int*)d_in[15];
    float* out = (float*)d_out;

    float *h, *q, *k, *v, *f1, *f3;
    cudaGetSymbolAddress((void**)&h, g_h);
    cudaGetSymbolAddress((void**)&q, g_q);
    cudaGetSymbolAddress((void**)&k, g_k);
    cudaGetSymbolAddress((void**)&v, g_v);
    cudaGetSymbolAddress((void**)&f1, g_f1);
    cudaGetSymbolAddress((void**)&f3, g_f3);
    __nv_bfloat16 *wtH, *wtL, *xH, *xL, *hnH, *hnL, *attH, *attL, *f1H, *f1L;
    cudaGetSymbolAddress((void**)&wtH, g_wtH);
    cudaGetSymbolAddress((void**)&wtL, g_wtL);
    cudaGetSymbolAddress((void**)&xH, g_xH);
    cudaGetSymbolAddress((void**)&xL, g_xL);
    cudaGetSymbolAddress((void**)&hnH, g_hnH);
    cudaGetSymbolAddress((void**)&hnL, g_hnL);
    cudaGetSymbolAddress((void**)&attH, g_attH);
    cudaGetSymbolAddress((void**)&attL, g_attL);
    cudaGetSymbolAddress((void**)&f1H, g_f1H);
    cudaGetSymbolAddress((void**)&f1L, g_f1L);

    const int SMT = 1024 + N_STG * 65536;    // 197632
    cudaFuncSetAttribute(tg_kernel<false, true>,
                         cudaFuncAttributeMaxDynamicSharedMemorySize, SMT);
    cudaFuncSetAttribute(tg_kernel<true, false>,
                         cudaFuncAttributeMaxDynamicSharedMemorySize, SMT);
    cudaFuncSetAttribute(tg_kernel<false, false>,
                         cudaFuncAttributeMaxDynamicSharedMemorySize, SMT);
    cudaFuncSetAttribute(qkv_kernel,
                         cudaFuncAttributeMaxDynamicSharedMemorySize, SMT);
    cudaFuncSetAttribute(w13_kernel,
                         cudaFuncAttributeMaxDynamicSharedMemorySize, SMT);

    dim3 tb(32, 8);
    transpose_split<<<dim3(32, 32, 4), tb>>>(wq, wtH + OFF_WQ, wtL + OFF_WQ,
        D_MODEL, D_MODEL, (size_t)D_MODEL * D_MODEL, 1048576ULL);
    transpose_split<<<dim3(32, 32, 4), tb>>>(wk, wtH + OFF_WK, wtL + OFF_WK,
        D_MODEL, D_MODEL, (size_t)D_MODEL * D_MODEL, 1048576ULL);
    transpose_split<<<dim3(32, 32, 4), tb>>>(wv, wtH + OFF_WV, wtL + OFF_WV,
        D_MODEL, D_MODEL, (size_t)D_MODEL * D_MODEL, 1048576ULL);
    transpose_split<<<dim3(32, 32, 4), tb>>>(wo, wtH + OFF_WO, wtL + OFF_WO,
        D_MODEL, D_MODEL, (size_t)D_MODEL * D_MODEL, 1048576ULL);
    transpose_split<<<dim3(128, 32, 4), tb>>>(w1, wtH + OFF_W1, wtL + OFF_W1,
        D_MODEL, FFN_DIM, (size_t)D_MODEL * FFN_DIM, 4194304ULL);
    transpose_split<<<dim3(128, 32, 4), tb>>>(w3, wtH + OFF_W3, wtL + OFF_W3,
        D_MODEL, FFN_DIM, (size_t)D_MODEL * FFN_DIM, 4194304ULL);
    transpose_split<<<dim3(32, 128, 4), tb>>>(w2, wtH + OFF_W2, wtL + OFF_W2,
        FFN_DIM, D_MODEL, (size_t)FFN_DIM * D_MODEL, 4194304ULL);
    transpose_split<<<dim3(32, 2, 1), tb>>>(emb_w, wtH + OFF_EMB,
        wtL + OFF_EMB, IN_DIM, D_MODEL, 0ULL, 0ULL);
    transpose_split<<<dim3(4, 32, 1), tb>>>(out_w, wtH + OFF_OUT,
        wtL + OFF_OUT, D_MODEL, OUT_DIM, 0ULL, 0ULL);

    x_split_kernel<<<(S_LEN * IN_DIM + 255) / 256, 256>>>(x);

    // embed: h = x @ emb_w + emb_b   (K=64 -> single stage)
    tg_kernel<false, true><<<dim3(8, 16), 256, SMT>>>(
        xH, xL, wtH + OFF_EMB, wtL + OFF_EMB, emb_b, h,
        S_LEN, D_MODEL, IN_DIM);

    for (int l = 0; l < N_LAYERS; l++) {
        size_t oq = OFF_WQ + (size_t)l * 1048576;
        size_t ok = OFF_WK + (size_t)l * 1048576;
        size_t ov = OFF_WV + (size_t)l * 1048576;
        size_t oo = OFF_WO + (size_t)l * 1048576;
        size_t o1 = OFF_W1 + (size_t)l * 4194304;
        size_t o3 = OFF_W3 + (size_t)l * 4194304;
        size_t o2 = OFF_W2 + (size_t)l * 4194304;

        rmsnorm_split_kernel<<<S_LEN, 256>>>(h, attn_norm_w + l * D_MODEL,
                                             hnH, hnL);

        qkv_kernel<<<dim3(8, 16, 3), 256, SMT>>>(hnH, hnL, oq, ok, ov,
                                                 q, k, v);

        rope_kernel<<<(S_LEN * N_HEADS * 32) / 256, 256>>>(q, k, tok_id);

        attention_kernel<<<dim3(N_DOCS, N_HEADS), 256>>>(q, k, v, attH, attL);

        tg_kernel<true, false><<<dim3(8, 16), 256, SMT>>>(
            attH, attL, wtH + oo, wtL + oo, nullptr, h,
            S_LEN, D_MODEL, D_MODEL);

        rmsnorm_split_kernel<<<S_LEN, 256>>>(h, ffn_norm_w + l * D_MODEL,
                                             hnH, hnL);

        w13_kernel<<<dim3(32, 16, 2), 256, SMT>>>(hnH, hnL, o1, o3, f1, f3);

        silu_mul_kernel<<<(S_LEN * FFN_DIM / 4 + 255) / 256, 256>>>(
            f1, f3, f1H, f1L, S_LEN * FFN_DIM / 4);

        tg_kernel<true, false><<<dim3(8, 16), 256, SMT>>>(
            f1H, f1L, wtH + o2, wtL + o2, nullptr, h,
            S_LEN, D_MODEL, FFN_DIM);
    }

    rmsnorm_split_kernel<<<S_LEN, 256>>>(h, out_norm_w, hnH, hnL);
    tg_kernel<false, false><<<dim3(1, 16), 256, SMT>>>(
        hnH, hnL, wtH + OFF_OUT, wtL + OFF_OUT, nullptr, out,
        S_LEN, OUT_DIM, D_MODEL);
}

// round 10
// speedup vs baseline: 1.5896x; 1.0031x over previous
#include <cuda_runtime.h>
#include <cuda_bf16.h>
#include <math.h>
#include <stdint.h>

#define S_LEN 2048
#define D_MODEL 1024
#define N_HEADS 16
#define HEAD_DIM 64
#define FFN_DIM 4096
#define N_LAYERS 4
#define IN_DIM 64
#define OUT_DIM 128
#define DOC_LEN 256
#define N_DOCS 8
#define WIN 128

// ---------------- fp32 scratch ----------------
__device__ float g_h [S_LEN * D_MODEL];
__device__ float g_q [S_LEN * D_MODEL];
__device__ float g_k [S_LEN * D_MODEL];
__device__ float g_v [S_LEN * D_MODEL];
__device__ float g_f1[S_LEN * FFN_DIM];
__device__ float g_f3[S_LEN * FFN_DIM];

// ---------------- bf16 split planes, K-tiled + SW128 pre-swizzled --------
// byte_addr(row,k,R) = ((k>>6)*(R>>3) + (row>>3))*1024 + swz((row&7)*128+(k&63)*2)
#define OFF_WQ  0ULL
#define OFF_WK  4194304ULL
#define OFF_WV  8388608ULL
#define OFF_WO  12582912ULL
#define OFF_W1  16777216ULL
#define OFF_W3  33554432ULL
#define OFF_W2  50331648ULL
#define OFF_EMB 67108864ULL
#define OFF_OUT 67174400ULL
#define WT_TOTAL 67305472ULL
__device__ __align__(1024) __nv_bfloat16 g_wtH[WT_TOTAL];
__device__ __align__(1024) __nv_bfloat16 g_wtL[WT_TOTAL];
__device__ __align__(1024) __nv_bfloat16 g_xH[S_LEN * IN_DIM];
__device__ __align__(1024) __nv_bfloat16 g_xL[S_LEN * IN_DIM];
__device__ __align__(1024) __nv_bfloat16 g_hnH[S_LEN * D_MODEL];
__device__ __align__(1024) __nv_bfloat16 g_hnL[S_LEN * D_MODEL];
__device__ __align__(1024) __nv_bfloat16 g_attH[S_LEN * D_MODEL];
__device__ __align__(1024) __nv_bfloat16 g_attL[S_LEN * D_MODEL];
__device__ __align__(1024) __nv_bfloat16 g_f1H[S_LEN * FFN_DIM];
__device__ __align__(1024) __nv_bfloat16 g_f1L[S_LEN * FFN_DIM];

__device__ __forceinline__ void bsplit(float x, __nv_bfloat16& h,
                                       __nv_bfloat16& l) {
    h = __float2bfloat16_rn(x);
    l = __float2bfloat16_rn(x - __bfloat162float(h));
}
__device__ __forceinline__ size_t kt_addr(int row, int k, int R) {
    uint32_t off = (uint32_t)((row & 7) * 128 + (k & 63) * 2);
    uint32_t sw = off ^ ((off >> 3) & 0x70);
    return ((size_t)(k >> 6) * (R >> 3) + (row >> 3)) * 1024 + sw;
}
#define MBAR_INIT(a, c) \
    asm volatile("mbarrier.init.shared.b64 [%0], %1;" :: "r"(a), "r"(c) : "memory")
#define MBAR_EXPECT_TX(a, b) \
    asm volatile("mbarrier.arrive.expect_tx.shared.b64 _, [%0], %1;" \
                 :: "r"(a), "r"(b) : "memory")
#define MBAR_WAIT(a, ph) do {                                                 \
    asm volatile("{\n\t.reg .pred P1;\n\tWL_%=:\n\t"                          \
        "mbarrier.try_wait.parity.acquire.cta.shared::cta.b64 P1, [%0], %1, 0x989680;\n\t" \
        "@P1 bra.uni WD_%=;\n\tbra.uni WL_%=;\n\tWD_%=:\n\t}"                 \
        :: "r"(a), "r"(ph) : "memory");                                       \
} while (0)
__device__ __forceinline__ void bulk_g2s(uint32_t dst, const void* src,
                                         uint32_t bytes, uint32_t mbar) {
    asm volatile(
        "cp.async.bulk.shared::cluster.global.mbarrier::complete_tx::bytes "
        "[%0], [%1], %2, [%3];"
        :: "r"(dst), "l"(src), "r"(bytes), "r"(mbar) : "memory");
}
__device__ __forceinline__ void mma_bf16(float* d, const uint32_t* a,
                                         const uint32_t* b) {
    asm volatile(
        "mma.sync.aligned.m16n8k16.row.col.f32.bf16.bf16.f32 "
        "{%0,%1,%2,%3}, {%4,%5,%6,%7}, {%8,%9}, {%0,%1,%2,%3};\n"
        : "+f"(d[0]), "+f"(d[1]), "+f"(d[2]), "+f"(d[3])
        : "r"(a[0]), "r"(a[1]), "r"(a[2]), "r"(a[3]), "r"(b[0]), "r"(b[1]));
}
__device__ __forceinline__ void ldsm4(uint32_t* r, uint32_t addr) {
    asm volatile(
        "ldmatrix.sync.aligned.m8n8.x4.shared.b16 {%0,%1,%2,%3}, [%4];"
        : "=r"(r[0]), "=r"(r[1]), "=r"(r[2]), "=r"(r[3]) : "r"(addr));
}

// ============== bulk-copy + ldmatrix + mma.sync GEMM ==============
// C[M,N] = A @ B^T; A planes [M][K] kt-layout, B planes [N][K] kt-layout.
// CTA 128x128x64-per-stage, 16 warps (4x4), warp 32x32, 3-term bf16 split.
// stage = A_H|A_L|B_H|B_L, 16KB each. 3 stages. Data at smem+1024.
#define STG_B 65536u
#define N_STG 3

template <bool ADD, bool BIAS>
__device__ __forceinline__ void tc_core(
    const __nv_bfloat16* __restrict__ AH, const __nv_bfloat16* __restrict__ AL,
    const __nv_bfloat16* __restrict__ BH, const __nv_bfloat16* __restrict__ BL,
    const float* __restrict__ bias, float* __restrict__ C,
    int M, int N, int K) {
    extern __shared__ char smem[];
    const int tid = threadIdx.x;
    const int lane = tid & 31;
    const int w = tid >> 5;
    const int wm = w & 3;             // 0..3 -> 32-row slab
    const int wn = w >> 2;            // 0..3 -> 32-col slab
    const int rowBase = blockIdx.y * 128;
    const int colBase = blockIdx.x * 128;
    const int ac = lane & 3;
    const int lr = lane >> 2;

    uint32_t sb = (uint32_t)__cvta_generic_to_shared(smem);
    uint32_t mb_full[N_STG] = { sb + 8, sb + 16, sb + 24 };

    if (tid == 0) {
        MBAR_INIT(mb_full[0], 1);
        MBAR_INIT(mb_full[1], 1);
        MBAR_INIT(mb_full[2], 1);
        asm volatile("fence.proxy.async.shared::cta;" ::: "memory");
    }
    __syncthreads();

    const int S = K >> 6;

    auto load_stage = [&](int s) {
        uint32_t d = sb + 1024 + (uint32_t)(s % N_STG) * STG_B;
        uint32_t fb = mb_full[s % N_STG];
        size_t aoff = ((size_t)s * (M >> 3) + (rowBase >> 3)) * 1024;
        size_t boff = ((size_t)s * (N >> 3) + (colBase >> 3)) * 1024;
        MBAR_EXPECT_TX(fb, STG_B);
        bulk_g2s(d, (const char*)AH + aoff, 16384, fb);
        bulk_g2s(d + 16384, (const char*)AL + aoff, 16384, fb);
        bulk_g2s(d + 32768, (const char*)BH + boff, 16384, fb);
        bulk_g2s(d + 49152, (const char*)BL + boff, 16384, fb);
    };

    if (tid == 0) {
        load_stage(0);
        if (S > 1) load_stage(1);
        if (S > 2) load_stage(2);
    }

    // ldmatrix per-thread address offsets (within a plane, per k16 chunk c)
    const int lm = lane >> 3;     // matrix index group
    const int rr = lane & 7;
    uint32_t aoffc[4], boffc[4];
#pragma unroll
    for (int c = 0; c < 4; c++) {
        uint32_t ao = (uint32_t)(rr * 128 + c * 32 + (lm >> 1) * 16);
        aoffc[c] = (uint32_t)((lm & 1) * 1024) + (ao ^ ((ao >> 3) & 0x70));
        uint32_t bo = (uint32_t)(rr * 128 + c * 32 + (lm & 1) * 16);
        boffc[c] = (uint32_t)((lm >> 1) * 1024) + (bo ^ ((bo >> 3) & 0x70));
    }

    float acc[2][4][4];
#pragma unroll
    for (int i = 0; i < 2; i++)
#pragma unroll
        for (int j = 0; j < 4; j++)
#pragma unroll
            for (int t = 0; t < 4; t++) acc[i][j][t] = 0.f;

    const uint32_t bB = (uint32_t)(wn * 4) * 1024;

    for (int s = 0; s < S; s++) {
        MBAR_WAIT(mb_full[s % N_STG], (s / N_STG) & 1);
        uint32_t stg = sb + 1024 + (uint32_t)(s % N_STG) * STG_B;
        uint32_t pAH = stg;
        uint32_t pAL = stg + 16384;
        uint32_t pBH = stg + 32768;
        uint32_t pBL = stg + 49152;

#pragma unroll
        for (int c = 0; c < 4; c++) {           // k16 chunk
            uint32_t bh[8], bl[8];              // [2*j], [2*j+1]
            ldsm4(bh,     pBH + bB + boffc[c]);
            ldsm4(bh + 4, pBH + bB + 2048 + boffc[c]);
            ldsm4(bl,     pBL + bB + boffc[c]);
            ldsm4(bl + 4, pBL + bB + 2048 + boffc[c]);
            uint32_t ah[2][4], al[2][4];
#pragma unroll
            for (int i = 0; i < 2; i++) {
                uint32_t aB = (uint32_t)(wm * 4 + i * 2) * 1024;
                ldsm4(ah[i], pAH + aB + aoffc[c]);
                ldsm4(al[i], pAL + aB + aoffc[c]);
            }
            // three de-chained passes: each acc re-touched after 8 indep MMAs
#pragma unroll
            for (int i = 0; i < 2; i++)
#pragma unroll
                for (int j = 0; j < 4; j++)
                    mma_bf16(acc[i][j], al[i], bh + 2 * j);
#pragma unroll
            for (int i = 0; i < 2; i++)
#pragma unroll
                for (int j = 0; j < 4; j++)
                    mma_bf16(acc[i][j], ah[i], bl + 2 * j);
#pragma unroll
            for (int i = 0; i < 2; i++)
#pragma unroll
                for (int j = 0; j < 4; j++)
                    mma_bf16(acc[i][j], ah[i], bh + 2 * j);
        }
        __syncthreads();
        if (tid == 0 && s + N_STG < S) load_stage(s + N_STG);
    }

    // epilogue (m16n8 acc: c0,c1 @ (lr, 2ac); c2,c3 @ (lr+8, 2ac))
#pragma unroll
    for (int i = 0; i < 2; i++) {
        int r0 = rowBase + wm * 32 + i * 16 + lr;
#pragma unroll
        for (int j = 0; j < 4; j++) {
            int c0 = colBase + wn * 32 + j * 8 + ac * 2;
            float2 v0 = make_float2(acc[i][j][0], acc[i][j][1]);
            float2 v1 = make_float2(acc[i][j][2], acc[i][j][3]);
            if (BIAS) {
                float b0 = bias[c0], b1 = bias[c0 + 1];
                v0.x += b0; v0.y += b1; v1.x += b0; v1.y += b1;
            }
            float* p0 = C + (size_t)r0 * N + c0;
            float* p1 = C + (size_t)(r0 + 8) * N + c0;
            if (ADD) {
                float2 o0 = *(float2*)p0, o1 = *(float2*)p1;
                v0.x += o0.x; v0.y += o0.y;
                v1.x += o1.x; v1.y += o1.y;
            }
            *(float2*)p0 = v0;
            *(float2*)p1 = v1;
        }
    }
}

template <bool ADD, bool BIAS>
__global__ __launch_bounds__(512)
void tg_kernel(const __nv_bfloat16* AH, const __nv_bfloat16* AL,
               const __nv_bfloat16* BH, const __nv_bfloat16* BL,
               const float* bias, float* C, int M, int N, int K) {
    tc_core<ADD, BIAS>(AH, AL, BH, BL, bias, C, M, N, K);
}

__global__ __launch_bounds__(512)
void qkv_kernel(const __nv_bfloat16* AH, const __nv_bfloat16* AL,
                size_t oq, size_t ok, size_t ov,
                float* q, float* k, float* v) {
    size_t off = (blockIdx.z == 0) ? oq : (blockIdx.z == 1) ? ok : ov;
    float* C = (blockIdx.z == 0) ? q : (blockIdx.z == 1) ? k : v;
    tc_core<false, false>(AH, AL, g_wtH + off, g_wtL + off, nullptr, C,
                          S_LEN, D_MODEL, D_MODEL);
}

__global__ __launch_bounds__(512)
void w13_kernel(const __nv_bfloat16* AH, const __nv_bfloat16* AL,
                size_t o1, size_t o3, float* f1, float* f3) {
    size_t off = (blockIdx.z == 0) ? o1 : o3;
    float* C = (blockIdx.z == 0) ? f1 : f3;
    tc_core<false, false>(AH, AL, g_wtH + off, g_wtL + off, nullptr, C,
                          S_LEN, FFN_DIM, D_MODEL);
}

// ---------------- weight transpose + split into kt layout ----------------
__global__ void transpose_split(const float* __restrict__ src,
                                __nv_bfloat16* __restrict__ dH,
                                __nv_bfloat16* __restrict__ dL,
                                int K, int N, size_t srcStride,
                                size_t dstStride) {
    src += (size_t)blockIdx.z * srcStride;
    dH += (size_t)blockIdx.z * dstStride;
    dL += (size_t)blockIdx.z * dstStride;
    __shared__ float t[32][33];
    int x = blockIdx.x * 32 + threadIdx.x;
    int y0 = blockIdx.y * 32;
#pragma unroll
    for (int i = 0; i < 32; i += 8)
        t[threadIdx.y + i][threadIdx.x] =
            src[(size_t)(y0 + threadIdx.y + i) * N + x];
    __syncthreads();
    int n = blockIdx.x * 32 + threadIdx.y;
    int kk = y0 + threadIdx.x;
#pragma unroll
    for (int i = 0; i < 32; i += 8) {
        float v = t[threadIdx.x][threadIdx.y + i];
        __nv_bfloat16 h, l;
        bsplit(v, h, l);
        size_t a = kt_addr(n + i, kk, N);
        *(__nv_bfloat16*)((char*)dH + a) = h;
        *(__nv_bfloat16*)((char*)dL + a) = l;
    }
}

__global__ __launch_bounds__(256)
void x_split_kernel(const float* __restrict__ x) {
    int i = blockIdx.x * 256 + threadIdx.x;
    if (i < S_LEN * IN_DIM) {
        __nv_bfloat16 h, l;
        bsplit(x[i], h, l);
        size_t a = kt_addr(i >> 6, i & 63, S_LEN);
        *(__nv_bfloat16*)((char*)g_xH + a) = h;
        *(__nv_bfloat16*)((char*)g_xL + a) = l;
    }
}

__global__ __launch_bounds__(256)
void rmsnorm_split_kernel(const float* __restrict__ x,
                          const float* __restrict__ w,
                          __nv_bfloat16* __restrict__ yH,
                          __nv_bfloat16* __restrict__ yL) {
    int row = blockIdx.x;
    const float* xr = x + (size_t)row * D_MODEL;
    float s = 0.f;
    for (int i = threadIdx.x; i < D_MODEL; i += 256) {
        float v = xr[i];
        s += v * v;
    }
    __shared__ float red[8];
#pragma unroll
    for (int o = 16; o; o >>= 1) s += __shfl_xor_sync(0xffffffffu, s, o);
    if ((threadIdx.x & 31) == 0) red[threadIdx.x >> 5] = s;
    __syncthreads();
    if (threadIdx.x < 8) {
        float t = red[threadIdx.x];
#pragma unroll
        for (int o = 4; o; o >>= 1) t += __shfl_xor_sync(0xffu, t, o);
        if (threadIdx.x == 0) red[0] = rsqrtf(t / (float)D_MODEL + 1e-5f);
    }
    __syncthreads();
    float r = red[0];
    for (int i = threadIdx.x; i < D_MODEL; i += 256) {
        float v = xr[i] * r * w[i];
        __nv_bfloat16 h, l;
        bsplit(v, h, l);
        size_t a = kt_addr(row, i, S_LEN);
        *(__nv_bfloat16*)((char*)yH + a) = h;
        *(__nv_bfloat16*)((char*)yL + a) = l;
    }
}

__global__ __launch_bounds__(256)
void rope_kernel(float* __restrict__ q, float* __restrict__ k,
                 const int* __restrict__ tok_id) {
    int idx = blockIdx.x * 256 + threadIdx.x;
    if (idx >= S_LEN * N_HEADS * (HEAD_DIM / 2)) return;
    int j = idx & 31;
    int h = (idx >> 5) & 15;
    int s = idx >> 9;
    float t = (float)tok_id[s];
    float inv = expf(-logf(10000.f) * (float)(2 * j) / (float)HEAD_DIM);
    float ang = t * inv;
    float c = cosf(ang), sn = sinf(ang);
    int base = s * D_MODEL + h * HEAD_DIM + j;
    float q1 = q[base], q2 = q[base + 32];
    q[base] = q1 * c - q2 * sn;
    q[base + 32] = q1 * sn + q2 * c;
    float k1 = k[base], k2 = k[base + 32];
    k[base] = k1 * c - k2 * sn;
    k[base + 32] = k1 * sn + k2 * c;
}

__global__ __launch_bounds__(256)
void attention_kernel(const float* __restrict__ q, const float* __restrict__ k,
                      const float* __restrict__ v,
                      __nv_bfloat16* __restrict__ outH,
                      __nv_bfloat16* __restrict__ outL) {
    const int doc = blockIdx.x;
    const int head = blockIdx.y;
    const int qi = threadIdx.x;
    const int qg = doc * DOC_LEN + qi;

    __shared__ float Ks[64][64];
    __shared__ float Vs[64][64];

    float qreg[HEAD_DIM];
    const float scale = 0.125f;
    const float* qp = q + (size_t)qg * D_MODEL + head * HEAD_DIM;
#pragma unroll
    for (int d = 0; d < HEAD_DIM; d += 4) {
        float4 t = *(const float4*)&qp[d];
        qreg[d] = t.x * scale; qreg[d + 1] = t.y * scale;
        qreg[d + 2] = t.z * scale; qreg[d + 3] = t.w * scale;
    }

    float o[HEAD_DIM];
#pragma unroll
    for (int d = 0; d < HEAD_DIM; d++) o[d] = 0.f;
    float m = -1e30f, l = 0.f;

    for (int kt = 0; kt < 4; kt++) {
        __syncthreads();
        for (int f = threadIdx.x; f < 1024; f += 256) {
            int r = f >> 4;
            int c = (f & 15) << 2;
            int kg = doc * DOC_LEN + kt * 64 + r;
            *(float4*)&Ks[r][c] =
                *(const float4*)&k[(size_t)kg * D_MODEL + head * HEAD_DIM + c];
            *(float4*)&Vs[r][c] =
                *(const float4*)&v[(size_t)kg * D_MODEL + head * HEAD_DIM + c];
        }
        __syncthreads();

        for (int j = 0; j < 64; j++) {
            int tk = kt * 64 + j;
            int dlt = qi - tk;
            if (dlt < 0) dlt = -dlt;
            if (dlt < WIN) {
                float s = 0.f;
#pragma unroll
                for (int d = 0; d < HEAD_DIM; d++) s += qreg[d] * Ks[j][d];
                float mn = fmaxf(m, s);
                float corr = expf(m - mn);
                float p = expf(s - mn);
                l = l * corr + p;
#pragma unroll
                for (int d = 0; d < HEAD_DIM; d++)
                    o[d] = o[d] * corr + p * Vs[j][d];
                m = mn;
            }
        }
    }

    float invl = 1.f / l;
#pragma unroll
    for (int d = 0; d < HEAD_DIM; d++) {
        __nv_bfloat16 h, lo;
        bsplit(o[d] * invl, h, lo);
        size_t a = kt_addr(qg, head * HEAD_DIM + d, S_LEN);
        *(__nv_bfloat16*)((char*)outH + a) = h;
        *(__nv_bfloat16*)((char*)outL + a) = lo;
    }
}

__global__ __launch_bounds__(256)
void silu_mul_kernel(const float* __restrict__ f1, const float* __restrict__ f3,
                     __nv_bfloat16* __restrict__ oH,
                     __nv_bfloat16* __restrict__ oL, int n4) {
    int i = blockIdx.x * 256 + threadIdx.x;
    if (i < n4) {
        float4 a = ((const float4*)f1)[i];
        float4 b = ((const float4*)f3)[i];
        float r[4];
        r[0] = (a.x / (1.f + expf(-a.x))) * b.x;
        r[1] = (a.y / (1.f + expf(-a.y))) * b.y;
        r[2] = (a.z / (1.f + expf(-a.z))) * b.z;
        r[3] = (a.w / (1.f + expf(-a.w))) * b.w;
#pragma unroll
        for (int t = 0; t < 4; t++) {
            int e = i * 4 + t;
            __nv_bfloat16 h, l;
            bsplit(r[t], h, l);
            size_t adr = kt_addr(e >> 12, e & 4095, S_LEN);
            *(__nv_bfloat16*)((char*)oH + adr) = h;
            *(__nv_bfloat16*)((char*)oL + adr) = l;
        }
    }
}

// ---------------- host orchestration ----------------
extern "C" void kernel_launch(void* const* d_in, const int* in_sizes, int n_in,
                              void* d_out, int out_size) {
    const float* x           = (const float*)d_in[0];
    const float* emb_w       = (const float*)d_in[1];
    const float* emb_b       = (const float*)d_in[2];
    const float* wq          = (const float*)d_in[3];
    const float* wk          = (const float*)d_in[4];
    const float* wv          = (const float*)d_in[5];
    const float* wo          = (const float*)d_in[6];
    const float* attn_norm_w = (const float*)d_in[7];
    const float* ffn_norm_w  = (const float*)d_in[8];
    const float* w1          = (const float*)d_in[9];
    const float* w2          = (const float*)d_in[10];
    const float* w3          = (const float*)d_in[11];
    const float* out_norm_w  = (const float*)d_in[12];
    const float* out_w       = (const float*)d_in[13];
    const int*   tok_id      = (const int*)d_in[15];
    float* out = (float*)d_out;

    float *h, *q, *k, *v, *f1, *f3;
    cudaGetSymbolAddress((void**)&h, g_h);
    cudaGetSymbolAddress((void**)&q, g_q);
    cudaGetSymbolAddress((void**)&k, g_k);
    cudaGetSymbolAddress((void**)&v, g_v);
    cudaGetSymbolAddress((void**)&f1, g_f1);
    cudaGetSymbolAddress((void**)&f3, g_f3);
    __nv_bfloat16 *wtH, *wtL, *xH, *xL, *hnH, *hnL, *attH, *attL, *f1H, *f1L;
    cudaGetSymbolAddress((void**)&wtH, g_wtH);
    cudaGetSymbolAddress((void**)&wtL, g_wtL);
    cudaGetSymbolAddress((void**)&xH, g_xH);
    cudaGetSymbolAddress((void**)&xL, g_xL);
    cudaGetSymbolAddress((void**)&hnH, g_hnH);
    cudaGetSymbolAddress((void**)&hnL, g_hnL);
    cudaGetSymbolAddress((void**)&attH, g_attH);
    cudaGetSymbolAddress((void**)&attL, g_attL);
    cudaGetSymbolAddress((void**)&f1H, g_f1H);
    cudaGetSymbolAddress((void**)&f1L, g_f1L);

    const int SMT = 1024 + N_STG * 65536;    // 197632
    cudaFuncSetAttribute(tg_kernel<false, true>,
                         cudaFuncAttributeMaxDynamicSharedMemorySize, SMT);
    cudaFuncSetAttribute(tg_kernel<true, false>,
                         cudaFuncAttributeMaxDynamicSharedMemorySize, SMT);
    cudaFuncSetAttribute(tg_kernel<false, false>,
                         cudaFuncAttributeMaxDynamicSharedMemorySize, SMT);
    cudaFuncSetAttribute(qkv_kernel,
                         cudaFuncAttributeMaxDynamicSharedMemorySize, SMT);
    cudaFuncSetAttribute(w13_kernel,
                         cudaFuncAttributeMaxDynamicSharedMemorySize, SMT);

    dim3 tb(32, 8);
    transpose_split<<<dim3(32, 32, 4), tb>>>(wq, wtH + OFF_WQ, wtL + OFF_WQ,
        D_MODEL, D_MODEL, (size_t)D_MODEL * D_MODEL, 1048576ULL);
    transpose_split<<<dim3(32, 32, 4), tb>>>(wk, wtH + OFF_WK, wtL + OFF_WK,
        D_MODEL, D_MODEL, (size_t)D_MODEL * D_MODEL, 1048576ULL);
    transpose_split<<<dim3(32, 32, 4), tb>>>(wv, wtH + OFF_WV, wtL + OFF_WV,
        D_MODEL, D_MODEL, (size_t)D_MODEL * D_MODEL, 1048576ULL);
    transpose_split<<<dim3(32, 32, 4), tb>>>(wo, wtH + OFF_WO, wtL + OFF_WO,
        D_MODEL, D_MODEL, (size_t)D_MODEL * D_MODEL, 1048576ULL);
    transpose_split<<<dim3(128, 32, 4), tb>>>(w1, wtH + OFF_W1, wtL + OFF_W1,
        D_MODEL, FFN_DIM, (size_t)D_MODEL * FFN_DIM, 4194304ULL);
    transpose_split<<<dim3(128, 32, 4), tb>>>(w3, wtH + OFF_W3, wtL + OFF_W3,
        D_MODEL, FFN_DIM, (size_t)D_MODEL * FFN_DIM, 4194304ULL);
    transpose_split<<<dim3(32, 128, 4), tb>>>(w2, wtH + OFF_W2, wtL + OFF_W2,
        FFN_DIM, D_MODEL, (size_t)FFN_DIM * D_MODEL, 4194304ULL);
    transpose_split<<<dim3(32, 2, 1), tb>>>(emb_w, wtH + OFF_EMB,
        wtL + OFF_EMB, IN_DIM, D_MODEL, 0ULL, 0ULL);
    transpose_split<<<dim3(4, 32, 1), tb>>>(out_w, wtH + OFF_OUT,
        wtL + OFF_OUT, D_MODEL, OUT_DIM, 0ULL, 0ULL);

    x_split_kernel<<<(S_LEN * IN_DIM + 255) / 256, 256>>>(x);

    // embed: h = x @ emb_w + emb_b   (K=64 -> single stage)
    tg_kernel<false, true><<<dim3(8, 16), 512, SMT>>>(
        xH, xL, wtH + OFF_EMB, wtL + OFF_EMB, emb_b, h,
        S_LEN, D_MODEL, IN_DIM);

    for (int l = 0; l < N_LAYERS; l++) {
        size_t oq = OFF_WQ + (size_t)l * 1048576;
        size_t ok = OFF_WK + (size_t)l * 1048576;
        size_t ov = OFF_WV + (size_t)l * 1048576;
        size_t oo = OFF_WO + (size_t)l * 1048576;
        size_t o1 = OFF_W1 + (size_t)l * 4194304;
        size_t o3 = OFF_W3 + (size_t)l * 4194304;
        size_t o2 = OFF_W2 + (size_t)l * 4194304;

        rmsnorm_split_kernel<<<S_LEN, 256>>>(h, attn_norm_w + l * D_MODEL,
                                             hnH, hnL);

        qkv_kernel<<<dim3(8, 16, 3), 512, SMT>>>(hnH, hnL, oq, ok, ov,
                                                 q, k, v);

        rope_kernel<<<(S_LEN * N_HEADS * 32) / 256, 256>>>(q, k, tok_id);

        attention_kernel<<<dim3(N_DOCS, N_HEADS), 256>>>(q, k, v, attH, attL);

        tg_kernel<true, false><<<dim3(8, 16), 512, SMT>>>(
            attH, attL, wtH + oo, wtL + oo, nullptr, h,
            S_LEN, D_MODEL, D_MODEL);

        rmsnorm_split_kernel<<<S_LEN, 256>>>(h, ffn_norm_w + l * D_MODEL,
                                             hnH, hnL);

        w13_kernel<<<dim3(32, 16, 2), 512, SMT>>>(hnH, hnL, o1, o3, f1, f3);

        silu_mul_kernel<<<(S_LEN * FFN_DIM / 4 + 255) / 256, 256>>>(
            f1, f3, f1H, f1L, S_LEN * FFN_DIM / 4);

        tg_kernel<true, false><<<dim3(8, 16), 512, SMT>>>(
            f1H, f1L, wtH + o2, wtL + o2, nullptr, h,
            S_LEN, D_MODEL, FFN_DIM);
    }

    rmsnorm_split_kernel<<<S_LEN, 256>>>(h, out_norm_w, hnH, hnL);
    tg_kernel<false, false><<<dim3(1, 16), 512, SMT>>>(
        hnH, hnL, wtH + OFF_OUT, wtL + OFF_OUT, nullptr, out,
        S_LEN, OUT_DIM, D_MODEL);
}

// round 12
// speedup vs baseline: 1.9094x; 1.2012x over previous
#include <cuda_runtime.h>
#include <cuda_fp16.h>
#include <math.h>
#include <stdint.h>

#define S_LEN 2048
#define D_MODEL 1024
#define N_HEADS 16
#define HEAD_DIM 64
#define FFN_DIM 4096
#define N_LAYERS 4
#define IN_DIM 64
#define OUT_DIM 128
#define DOC_LEN 256
#define N_DOCS 8
#define WIN 128

// ---------------- fp32 scratch ----------------
__device__ float g_h [S_LEN * D_MODEL];
__device__ float g_q [S_LEN * D_MODEL];
__device__ float g_k [S_LEN * D_MODEL];
__device__ float g_v [S_LEN * D_MODEL];
__device__ float g_f1[S_LEN * FFN_DIM];
__device__ float g_f3[S_LEN * FFN_DIM];

// ---------------- fp16 planes, K-tiled + SW128 pre-swizzled --------
// byte_addr(row,k,R) = ((k>>6)*(R>>3) + (row>>3))*1024 + swz((row&7)*128+(k&63)*2)
// Weights: single fp16 plane (transposed [N][K]).
// Activations: hi+lo fp16 planes.
#define OFF_WQ  0ULL
#define OFF_WK  4194304ULL
#define OFF_WV  8388608ULL
#define OFF_WO  12582912ULL
#define OFF_W1  16777216ULL
#define OFF_W3  33554432ULL
#define OFF_W2  50331648ULL
#define OFF_EMB 67108864ULL
#define OFF_OUT 67174400ULL
#define WT_TOTAL 67305472ULL
__device__ __align__(1024) __half g_wt[WT_TOTAL];
__device__ __align__(1024) __half g_xH[S_LEN * IN_DIM];
__device__ __align__(1024) __half g_xL[S_LEN * IN_DIM];
__device__ __align__(1024) __half g_hnH[S_LEN * D_MODEL];
__device__ __align__(1024) __half g_hnL[S_LEN * D_MODEL];
__device__ __align__(1024) __half g_attH[S_LEN * D_MODEL];
__device__ __align__(1024) __half g_attL[S_LEN * D_MODEL];
__device__ __align__(1024) __half g_f1H[S_LEN * FFN_DIM];
__device__ __align__(1024) __half g_f1L[S_LEN * FFN_DIM];

__device__ __forceinline__ void hsplit(float x, __half& h, __half& l) {
    h = __float2half_rn(x);
    l = __float2half_rn(x - __half2float(h));
}
__device__ __forceinline__ size_t kt_addr(int row, int k, int R) {
    uint32_t off = (uint32_t)((row & 7) * 128 + (k & 63) * 2);
    uint32_t sw = off ^ ((off >> 3) & 0x70);
    return ((size_t)(k >> 6) * (R >> 3) + (row >> 3)) * 1024 + sw;
}
#define MBAR_INIT(a, c) \
    asm volatile("mbarrier.init.shared.b64 [%0], %1;" :: "r"(a), "r"(c) : "memory")
#define MBAR_EXPECT_TX(a, b) \
    asm volatile("mbarrier.arrive.expect_tx.shared.b64 _, [%0], %1;" \
                 :: "r"(a), "r"(b) : "memory")
#define MBAR_WAIT(a, ph) do {                                                 \
    asm volatile("{\n\t.reg .pred P1;\n\tWL_%=:\n\t"                          \
        "mbarrier.try_wait.parity.acquire.cta.shared::cta.b64 P1, [%0], %1, 0x989680;\n\t" \
        "@P1 bra.uni WD_%=;\n\tbra.uni WL_%=;\n\tWD_%=:\n\t}"                 \
        :: "r"(a), "r"(ph) : "memory");                                       \
} while (0)
__device__ __forceinline__ void bulk_g2s(uint32_t dst, const void* src,
                                         uint32_t bytes, uint32_t mbar) {
    asm volatile(
        "cp.async.bulk.shared::cluster.global.mbarrier::complete_tx::bytes "
        "[%0], [%1], %2, [%3];"
        :: "r"(dst), "l"(src), "r"(bytes), "r"(mbar) : "memory");
}
__device__ __forceinline__ void mma_f16(float* d, const uint32_t* a,
                                        const uint32_t* b) {
    asm volatile(
        "mma.sync.aligned.m16n8k16.row.col.f32.f16.f16.f32 "
        "{%0,%1,%2,%3}, {%4,%5,%6,%7}, {%8,%9}, {%0,%1,%2,%3};\n"
        : "+f"(d[0]), "+f"(d[1]), "+f"(d[2]), "+f"(d[3])
        : "r"(a[0]), "r"(a[1]), "r"(a[2]), "r"(a[3]), "r"(b[0]), "r"(b[1]));
}
__device__ __forceinline__ void ldsm4(uint32_t* r, uint32_t addr) {
    asm volatile(
        "ldmatrix.sync.aligned.m8n8.x4.shared.b16 {%0,%1,%2,%3}, [%4];"
        : "=r"(r[0]), "=r"(r[1]), "=r"(r[2]), "=r"(r[3]) : "r"(addr));
}

// ============== bulk-copy + ldmatrix + mma.sync fp16 GEMM ==============
// C[M,N] = A @ B^T; A hi/lo planes [M][K] kt-layout, B single plane [N][K].
// CTA 128x128x64-per-stage, 16 warps (4x4), warp 32x32, 2-term fp16 split:
//   acc += al*b ; acc += ah*b     (weights fp16, activations ~22-bit)
// stage = A_H|A_L|B, 16KB each. 3 stages. Data at smem+1024.
#define STG_B 49152u
#define N_STG 3

template <bool ADD, bool BIAS>
__device__ __forceinline__ void tc_core(
    const __half* __restrict__ AH, const __half* __restrict__ AL,
    const __half* __restrict__ B,
    const float* __restrict__ bias, float* __restrict__ C,
    int M, int N, int K) {
    extern __shared__ char smem[];
    const int tid = threadIdx.x;
    const int lane = tid & 31;
    const int w = tid >> 5;
    const int wm = w & 3;             // 0..3 -> 32-row slab
    const int wn = w >> 2;            // 0..3 -> 32-col slab
    const int rowBase = blockIdx.y * 128;
    const int colBase = blockIdx.x * 128;
    const int ac = lane & 3;
    const int lr = lane >> 2;

    uint32_t sb = (uint32_t)__cvta_generic_to_shared(smem);
    uint32_t mb_full[N_STG] = { sb + 8, sb + 16, sb + 24 };

    if (tid == 0) {
        MBAR_INIT(mb_full[0], 1);
        MBAR_INIT(mb_full[1], 1);
        MBAR_INIT(mb_full[2], 1);
        asm volatile("fence.proxy.async.shared::cta;" ::: "memory");
    }
    __syncthreads();

    const int S = K >> 6;

    auto load_stage = [&](int s) {
        uint32_t d = sb + 1024 + (uint32_t)(s % N_STG) * STG_B;
        uint32_t fb = mb_full[s % N_STG];
        size_t aoff = ((size_t)s * (M >> 3) + (rowBase >> 3)) * 1024;
        size_t boff = ((size_t)s * (N >> 3) + (colBase >> 3)) * 1024;
        MBAR_EXPECT_TX(fb, STG_B);
        bulk_g2s(d, (const char*)AH + aoff, 16384, fb);
        bulk_g2s(d + 16384, (const char*)AL + aoff, 16384, fb);
        bulk_g2s(d + 32768, (const char*)B + boff, 16384, fb);
    };

    if (tid == 0) {
        load_stage(0);
        if (S > 1) load_stage(1);
        if (S > 2) load_stage(2);
    }

    // ldmatrix per-thread address offsets (within a plane, per k16 chunk c)
    const int lm = lane >> 3;     // matrix index group
    const int rr = lane & 7;
    uint32_t aoffc[4], boffc[4];
#pragma unroll
    for (int c = 0; c < 4; c++) {
        uint32_t ao = (uint32_t)(rr * 128 + c * 32 + (lm >> 1) * 16);
        aoffc[c] = (uint32_t)((lm & 1) * 1024) + (ao ^ ((ao >> 3) & 0x70));
        uint32_t bo = (uint32_t)(rr * 128 + c * 32 + (lm & 1) * 16);
        boffc[c] = (uint32_t)((lm >> 1) * 1024) + (bo ^ ((bo >> 3) & 0x70));
    }

    float acc[2][4][4];
#pragma unroll
    for (int i = 0; i < 2; i++)
#pragma unroll
        for (int j = 0; j < 4; j++)
#pragma unroll
            for (int t = 0; t < 4; t++) acc[i][j][t] = 0.f;

    const uint32_t bB = (uint32_t)(wn * 4) * 1024;

    for (int s = 0; s < S; s++) {
        MBAR_WAIT(mb_full[s % N_STG], (s / N_STG) & 1);
        uint32_t stg = sb + 1024 + (uint32_t)(s % N_STG) * STG_B;
        uint32_t pAH = stg;
        uint32_t pAL = stg + 16384;
        uint32_t pB  = stg + 32768;

#pragma unroll
        for (int c = 0; c < 4; c++) {           // k16 chunk
            uint32_t bf[8];                     // [2*j], [2*j+1]
            ldsm4(bf,     pB + bB + boffc[c]);
            ldsm4(bf + 4, pB + bB + 2048 + boffc[c]);
            uint32_t ah[2][4], al[2][4];
#pragma unroll
            for (int i = 0; i < 2; i++) {
                uint32_t aB = (uint32_t)(wm * 4 + i * 2) * 1024;
                ldsm4(ah[i], pAH + aB + aoffc[c]);
                ldsm4(al[i], pAL + aB + aoffc[c]);
            }
            // two de-chained passes: each acc re-touched after 8 indep MMAs
#pragma unroll
            for (int i = 0; i < 2; i++)
#pragma unroll
                for (int j = 0; j < 4; j++)
                    mma_f16(acc[i][j], al[i], bf + 2 * j);
#pragma unroll
            for (int i = 0; i < 2; i++)
#pragma unroll
                for (int j = 0; j < 4; j++)
                    mma_f16(acc[i][j], ah[i], bf + 2 * j);
        }
        __syncthreads();
        if (tid == 0 && s + N_STG < S) load_stage(s + N_STG);
    }

    // epilogue (m16n8 acc: c0,c1 @ (lr, 2ac); c2,c3 @ (lr+8, 2ac))
#pragma unroll
    for (int i = 0; i < 2; i++) {
        int r0 = rowBase + wm * 32 + i * 16 + lr;
#pragma unroll
        for (int j = 0; j < 4; j++) {
            int c0 = colBase + wn * 32 + j * 8 + ac * 2;
            float2 v0 = make_float2(acc[i][j][0], acc[i][j][1]);
            float2 v1 = make_float2(acc[i][j][2], acc[i][j][3]);
            if (BIAS) {
                float b0 = bias[c0], b1 = bias[c0 + 1];
                v0.x += b0; v0.y += b1; v1.x += b0; v1.y += b1;
            }
            float* p0 = C + (size_t)r0 * N + c0;
            float* p1 = C + (size_t)(r0 + 8) * N + c0;
            if (ADD) {
                float2 o0 = *(float2*)p0, o1 = *(float2*)p1;
                v0.x += o0.x; v0.y += o0.y;
                v1.x += o1.x; v1.y += o1.y;
            }
            *(float2*)p0 = v0;
            *(float2*)p1 = v1;
        }
    }
}

template <bool ADD, bool BIAS>
__global__ __launch_bounds__(512)
void tg_kernel(const __half* AH, const __half* AL, const __half* B,
               const float* bias, float* C, int M, int N, int K) {
    tc_core<ADD, BIAS>(AH, AL, B, bias, C, M, N, K);
}

__global__ __launch_bounds__(512)
void qkv_kernel(const __half* AH, const __half* AL,
                size_t oq, size_t ok, size_t ov,
                float* q, float* k, float* v) {
    size_t off = (blockIdx.z == 0) ? oq : (blockIdx.z == 1) ? ok : ov;
    float* C = (blockIdx.z == 0) ? q : (blockIdx.z == 1) ? k : v;
    tc_core<false, false>(AH, AL, g_wt + off, nullptr, C,
                          S_LEN, D_MODEL, D_MODEL);
}

__global__ __launch_bounds__(512)
void w13_kernel(const __half* AH, const __half* AL,
                size_t o1, size_t o3, float* f1, float* f3) {
    size_t off = (blockIdx.z == 0) ? o1 : o3;
    float* C = (blockIdx.z == 0) ? f1 : f3;
    tc_core<false, false>(AH, AL, g_wt + off, nullptr, C,
                          S_LEN, FFN_DIM, D_MODEL);
}

// ---------------- weight transpose + fp16 convert into kt layout ----------
__global__ void transpose_split(const float* __restrict__ src,
                                __half* __restrict__ dst,
                                int K, int N, size_t srcStride,
                                size_t dstStride) {
    src += (size_t)blockIdx.z * srcStride;
    dst += (size_t)blockIdx.z * dstStride;
    __shared__ float t[32][33];
    int x = blockIdx.x * 32 + threadIdx.x;
    int y0 = blockIdx.y * 32;
#pragma unroll
    for (int i = 0; i < 32; i += 8)
        t[threadIdx.y + i][threadIdx.x] =
            src[(size_t)(y0 + threadIdx.y + i) * N + x];
    __syncthreads();
    int n = blockIdx.x * 32 + threadIdx.y;
    int kk = y0 + threadIdx.x;
#pragma unroll
    for (int i = 0; i < 32; i += 8) {
        float v = t[threadIdx.x][threadIdx.y + i];
        size_t a = kt_addr(n + i, kk, N);
        *(__half*)((char*)dst + a) = __float2half_rn(v);
    }
}

__global__ __launch_bounds__(256)
void x_split_kernel(const float* __restrict__ x) {
    int i = blockIdx.x * 256 + threadIdx.x;
    if (i < S_LEN * IN_DIM) {
        __half h, l;
        hsplit(x[i], h, l);
        size_t a = kt_addr(i >> 6, i & 63, S_LEN);
        *(__half*)((char*)g_xH + a) = h;
        *(__half*)((char*)g_xL + a) = l;
    }
}

__global__ __launch_bounds__(256)
void rmsnorm_split_kernel(const float* __restrict__ x,
                          const float* __restrict__ w,
                          __half* __restrict__ yH,
                          __half* __restrict__ yL) {
    int row = blockIdx.x;
    const float* xr = x + (size_t)row * D_MODEL;
    float s = 0.f;
    for (int i = threadIdx.x; i < D_MODEL; i += 256) {
        float v = xr[i];
        s += v * v;
    }
    __shared__ float red[8];
#pragma unroll
    for (int o = 16; o; o >>= 1) s += __shfl_xor_sync(0xffffffffu, s, o);
    if ((threadIdx.x & 31) == 0) red[threadIdx.x >> 5] = s;
    __syncthreads();
    if (threadIdx.x < 8) {
        float t = red[threadIdx.x];
#pragma unroll
        for (int o = 4; o; o >>= 1) t += __shfl_xor_sync(0xffu, t, o);
        if (threadIdx.x == 0) red[0] = rsqrtf(t / (float)D_MODEL + 1e-5f);
    }
    __syncthreads();
    float r = red[0];
    for (int i = threadIdx.x; i < D_MODEL; i += 256) {
        float v = xr[i] * r * w[i];
        __half h, l;
        hsplit(v, h, l);
        size_t a = kt_addr(row, i, S_LEN);
        *(__half*)((char*)yH + a) = h;
        *(__half*)((char*)yL + a) = l;
    }
}

__global__ __launch_bounds__(256)
void rope_kernel(float* __restrict__ q, float* __restrict__ k,
                 const int* __restrict__ tok_id) {
    int idx = blockIdx.x * 256 + threadIdx.x;
    if (idx >= S_LEN * N_HEADS * (HEAD_DIM / 2)) return;
    int j = idx & 31;
    int h = (idx >> 5) & 15;
    int s = idx >> 9;
    float t = (float)tok_id[s];
    float inv = expf(-logf(10000.f) * (float)(2 * j) / (float)HEAD_DIM);
    float ang = t * inv;
    float c = cosf(ang), sn = sinf(ang);
    int base = s * D_MODEL + h * HEAD_DIM + j;
    float q1 = q[base], q2 = q[base + 32];
    q[base] = q1 * c - q2 * sn;
    q[base + 32] = q1 * sn + q2 * c;
    float k1 = k[base], k2 = k[base + 32];
    k[base] = k1 * c - k2 * sn;
    k[base + 32] = k1 * sn + k2 * c;
}

__global__ __launch_bounds__(256)
void attention_kernel(const float* __restrict__ q, const float* __restrict__ k,
                      const float* __restrict__ v,
                      __half* __restrict__ outH,
                      __half* __restrict__ outL) {
    const int doc = blockIdx.x;
    const int head = blockIdx.y;
    const int qi = threadIdx.x;
    const int qg = doc * DOC_LEN + qi;

    __shared__ float Ks[64][64];
    __shared__ float Vs[64][64];

    float qreg[HEAD_DIM];
    const float scale = 0.125f;
    const float* qp = q + (size_t)qg * D_MODEL + head * HEAD_DIM;
#pragma unroll
    for (int d = 0; d < HEAD_DIM; d += 4) {
        float4 t = *(const float4*)&qp[d];
        qreg[d] = t.x * scale; qreg[d + 1] = t.y * scale;
        qreg[d + 2] = t.z * scale; qreg[d + 3] = t.w * scale;
    }

    float o[HEAD_DIM];
#pragma unroll
    for (int d = 0; d < HEAD_DIM; d++) o[d] = 0.f;
    float m = -1e30f, l = 0.f;

    for (int kt = 0; kt < 4; kt++) {
        __syncthreads();
        for (int f = threadIdx.x; f < 1024; f += 256) {
            int r = f >> 4;
            int c = (f & 15) << 2;
            int kg = doc * DOC_LEN + kt * 64 + r;
            *(float4*)&Ks[r][c] =
                *(const float4*)&k[(size_t)kg * D_MODEL + head * HEAD_DIM + c];
            *(float4*)&Vs[r][c] =
                *(const float4*)&v[(size_t)kg * D_MODEL + head * HEAD_DIM + c];
        }
        __syncthreads();

        for (int j = 0; j < 64; j++) {
            int tk = kt * 64 + j;
            int dlt = qi - tk;
            if (dlt < 0) dlt = -dlt;
            if (dlt < WIN) {
                float s = 0.f;
#pragma unroll
                for (int d = 0; d < HEAD_DIM; d++) s += qreg[d] * Ks[j][d];
                float mn = fmaxf(m, s);
                float corr = expf(m - mn);
                float p = expf(s - mn);
                l = l * corr + p;
#pragma unroll
                for (int d = 0; d < HEAD_DIM; d++)
                    o[d] = o[d] * corr + p * Vs[j][d];
                m = mn;
            }
        }
    }

    float invl = 1.f / l;
#pragma unroll
    for (int d = 0; d < HEAD_DIM; d++) {
        __half h, lo;
        hsplit(o[d] * invl, h, lo);
        size_t a = kt_addr(qg, head * HEAD_DIM + d, S_LEN);
        *(__half*)((char*)outH + a) = h;
        *(__half*)((char*)outL + a) = lo;
    }
}

__global__ __launch_bounds__(256)
void silu_mul_kernel(const float* __restrict__ f1, const float* __restrict__ f3,
                     __half* __restrict__ oH,
                     __half* __restrict__ oL, int n4) {
    int i = blockIdx.x * 256 + threadIdx.x;
    if (i < n4) {
        float4 a = ((const float4*)f1)[i];
        float4 b = ((const float4*)f3)[i];
        float r[4];
        r[0] = (a.x / (1.f + expf(-a.x))) * b.x;
        r[1] = (a.y / (1.f + expf(-a.y))) * b.y;
        r[2] = (a.z / (1.f + expf(-a.z))) * b.z;
        r[3] = (a.w / (1.f + expf(-a.w))) * b.w;
#pragma unroll
        for (int t = 0; t < 4; t++) {
            int e = i * 4 + t;
            __half h, l;
            hsplit(r[t], h, l);
            size_t adr = kt_addr(e >> 12, e & 4095, S_LEN);
            *(__half*)((char*)oH + adr) = h;
            *(__half*)((char*)oL + adr) = l;
        }
    }
}

// ---------------- host orchestration ----------------
extern "C" void kernel_launch(void* const* d_in, const int* in_sizes, int n_in,
                              void* d_out, int out_size) {
    const float* x           = (const float*)d_in[0];
    const float* emb_w       = (const float*)d_in[1];
    const float* emb_b       = (const float*)d_in[2];
    const float* wq          = (const float*)d_in[3];
    const float* wk          = (const float*)d_in[4];
    const float* wv          = (const float*)d_in[5];
    const float* wo          = (const float*)d_in[6];
    const float* attn_norm_w = (const float*)d_in[7];
    const float* ffn_norm_w  = (const float*)d_in[8];
    const float* w1          = (const float*)d_in[9];
    const float* w2          = (const float*)d_in[10];
    const float* w3          = (const float*)d_in[11];
    const float* out_norm_w  = (const float*)d_in[12];
    const float* out_w       = (const float*)d_in[13];
    const int*   tok_id      = (const int*)d_in[15];
    float* out = (float*)d_out;

    float *h, *q, *k, *v, *f1, *f3;
    cudaGetSymbolAddress((void**)&h, g_h);
    cudaGetSymbolAddress((void**)&q, g_q);
    cudaGetSymbolAddress((void**)&k, g_k);
    cudaGetSymbolAddress((void**)&v, g_v);
    cudaGetSymbolAddress((void**)&f1, g_f1);
    cudaGetSymbolAddress((void**)&f3, g_f3);
    __half *wt, *xH, *xL, *hnH, *hnL, *attH, *attL, *f1H, *f1L;
    cudaGetSymbolAddress((void**)&wt, g_wt);
    cudaGetSymbolAddress((void**)&xH, g_xH);
    cudaGetSymbolAddress((void**)&xL, g_xL);
    cudaGetSymbolAddress((void**)&hnH, g_hnH);
    cudaGetSymbolAddress((void**)&hnL, g_hnL);
    cudaGetSymbolAddress((void**)&attH, g_attH);
    cudaGetSymbolAddress((void**)&attL, g_attL);
    cudaGetSymbolAddress((void**)&f1H, g_f1H);
    cudaGetSymbolAddress((void**)&f1L, g_f1L);

    const int SMT = 1024 + N_STG * 49152;    // 148480
    cudaFuncSetAttribute(tg_kernel<false, true>,
                         cudaFuncAttributeMaxDynamicSharedMemorySize, SMT);
    cudaFuncSetAttribute(tg_kernel<true, false>,
                         cudaFuncAttributeMaxDynamicSharedMemorySize, SMT);
    cudaFuncSetAttribute(tg_kernel<false, false>,
                         cudaFuncAttributeMaxDynamicSharedMemorySize, SMT);
    cudaFuncSetAttribute(qkv_kernel,
                         cudaFuncAttributeMaxDynamicSharedMemorySize, SMT);
    cudaFuncSetAttribute(w13_kernel,
                         cudaFuncAttributeMaxDynamicSharedMemorySize, SMT);

    dim3 tb(32, 8);
    transpose_split<<<dim3(32, 32, 4), tb>>>(wq, wt + OFF_WQ,
        D_MODEL, D_MODEL, (size_t)D_MODEL * D_MODEL, 1048576ULL);
    transpose_split<<<dim3(32, 32, 4), tb>>>(wk, wt + OFF_WK,
        D_MODEL, D_MODEL, (size_t)D_MODEL * D_MODEL, 1048576ULL);
    transpose_split<<<dim3(32, 32, 4), tb>>>(wv, wt + OFF_WV,
        D_MODEL, D_MODEL, (size_t)D_MODEL * D_MODEL, 1048576ULL);
    transpose_split<<<dim3(32, 32, 4), tb>>>(wo, wt + OFF_WO,
        D_MODEL, D_MODEL, (size_t)D_MODEL * D_MODEL, 1048576ULL);
    transpose_split<<<dim3(128, 32, 4), tb>>>(w1, wt + OFF_W1,
        D_MODEL, FFN_DIM, (size_t)D_MODEL * FFN_DIM, 4194304ULL);
    transpose_split<<<dim3(128, 32, 4), tb>>>(w3, wt + OFF_W3,
        D_MODEL, FFN_DIM, (size_t)D_MODEL * FFN_DIM, 4194304ULL);
    transpose_split<<<dim3(32, 128, 4), tb>>>(w2, wt + OFF_W2,
        FFN_DIM, D_MODEL, (size_t)FFN_DIM * D_MODEL, 4194304ULL);
    transpose_split<<<dim3(32, 2, 1), tb>>>(emb_w, wt + OFF_EMB,
        IN_DIM, D_MODEL, 0ULL, 0ULL);
    transpose_split<<<dim3(4, 32, 1), tb>>>(out_w, wt + OFF_OUT,
        D_MODEL, OUT_DIM, 0ULL, 0ULL);

    x_split_kernel<<<(S_LEN * IN_DIM + 255) / 256, 256>>>(x);

    // embed: h = x @ emb_w + emb_b   (K=64 -> single stage)
    tg_kernel<false, true><<<dim3(8, 16), 512, SMT>>>(
        xH, xL, wt + OFF_EMB, emb_b, h, S_LEN, D_MODEL, IN_DIM);

    for (int l = 0; l < N_LAYERS; l++) {
        size_t oq = OFF_WQ + (size_t)l * 1048576;
        size_t ok = OFF_WK + (size_t)l * 1048576;
        size_t ov = OFF_WV + (size_t)l * 1048576;
        size_t oo = OFF_WO + (size_t)l * 1048576;
        size_t o1 = OFF_W1 + (size_t)l * 4194304;
        size_t o3 = OFF_W3 + (size_t)l * 4194304;
        size_t o2 = OFF_W2 + (size_t)l * 4194304;

        rmsnorm_split_kernel<<<S_LEN, 256>>>(h, attn_norm_w + l * D_MODEL,
                                             hnH, hnL);

        qkv_kernel<<<dim3(8, 16, 3), 512, SMT>>>(hnH, hnL, oq, ok, ov,
                                                 q, k, v);

        rope_kernel<<<(S_LEN * N_HEADS * 32) / 256, 256>>>(q, k, tok_id);

        attention_kernel<<<dim3(N_DOCS, N_HEADS), 256>>>(q, k, v, attH, attL);

        tg_kernel<true, false><<<dim3(8, 16), 512, SMT>>>(
            attH, attL, wt + oo, nullptr, h, S_LEN, D_MODEL, D_MODEL);

        rmsnorm_split_kernel<<<S_LEN, 256>>>(h, ffn_norm_w + l * D_MODEL,
                                             hnH, hnL);

        w13_kernel<<<dim3(32, 16, 2), 512, SMT>>>(hnH, hnL, o1, o3, f1, f3);

        silu_mul_kernel<<<(S_LEN * FFN_DIM / 4 + 255) / 256, 256>>>(
            f1, f3, f1H, f1L, S_LEN * FFN_DIM / 4);

        tg_kernel<true, false><<<dim3(8, 16), 512, SMT>>>(
            f1H, f1L, wt + o2, nullptr, h, S_LEN, D_MODEL, FFN_DIM);
    }

    rmsnorm_split_kernel<<<S_LEN, 256>>>(h, out_norm_w, hnH, hnL);
    tg_kernel<false, false><<<dim3(1, 16), 512, SMT>>>(
        hnH, hnL, wt + OFF_OUT, nullptr, out, S_LEN, OUT_DIM, D_MODEL);
}

// round 17
// speedup vs baseline: 2.0816x; 1.0902x over previous
#include <cuda_runtime.h>
#include <cuda_fp16.h>
#include <math.h>
#include <stdint.h>

#define S_LEN 2048
#define D_MODEL 1024
#define N_HEADS 16
#define HEAD_DIM 64
#define FFN_DIM 4096
#define N_LAYERS 4
#define IN_DIM 64
#define OUT_DIM 128
#define DOC_LEN 256
#define N_DOCS 8
#define WIN 128

// ---------------- fp32 scratch ----------------
__device__ float g_h [S_LEN * D_MODEL];
__device__ float g_q [S_LEN * D_MODEL];
__device__ float g_k [S_LEN * D_MODEL];
__device__ float g_v [S_LEN * D_MODEL];

// ---------------- fp16 planes, K-tiled + SW128 pre-swizzled --------
// byte_addr(row,k,R) = ((k>>6)*(R>>3) + (row>>3))*1024 + swz((row&7)*128+(k&63)*2)
#define OFF_WQ  0ULL
#define OFF_WK  4194304ULL
#define OFF_WV  8388608ULL
#define OFF_WO  12582912ULL
#define OFF_W1  16777216ULL
#define OFF_W3  33554432ULL
#define OFF_W2  50331648ULL
#define OFF_EMB 67108864ULL
#define OFF_OUT 67174400ULL
#define WT_TOTAL 67305472ULL
__device__ __align__(1024) __half g_wt[WT_TOTAL];
__device__ __align__(1024) __half g_xH[S_LEN * IN_DIM];
__device__ __align__(1024) __half g_xL[S_LEN * IN_DIM];
__device__ __align__(1024) __half g_hnH[S_LEN * D_MODEL];
__device__ __align__(1024) __half g_hnL[S_LEN * D_MODEL];
__device__ __align__(1024) __half g_attH[S_LEN * D_MODEL];
__device__ __align__(1024) __half g_attL[S_LEN * D_MODEL];
__device__ __align__(1024) __half g_f1H[S_LEN * FFN_DIM];
__device__ __align__(1024) __half g_f1L[S_LEN * FFN_DIM];

__device__ __forceinline__ void hsplit(float x, __half& h, __half& l) {
    h = __float2half_rn(x);
    l = __float2half_rn(x - __half2float(h));
}
__device__ __forceinline__ uint32_t swz(uint32_t off) {
    return off ^ ((off >> 3) & 0x70);
}
__device__ __forceinline__ size_t kt_addr(int row, int k, int R) {
    uint32_t off = (uint32_t)((row & 7) * 128 + (k & 63) * 2);
    return ((size_t)(k >> 6) * (R >> 3) + (row >> 3)) * 1024 + swz(off);
}
__device__ __forceinline__ uint32_t pack2h(float a, float b) {
    __half2 h = __floats2half2_rn(a, b);
    return *(uint32_t*)&h;
}
#define MBAR_INIT(a, c) \
    asm volatile("mbarrier.init.shared.b64 [%0], %1;" :: "r"(a), "r"(c) : "memory")
#define MBAR_EXPECT_TX(a, b) \
    asm volatile("mbarrier.arrive.expect_tx.shared.b64 _, [%0], %1;" \
                 :: "r"(a), "r"(b) : "memory")
#define MBAR_WAIT(a, ph) do {                                                 \
    asm volatile("{\n\t.reg .pred P1;\n\tWL_%=:\n\t"                          \
        "mbarrier.try_wait.parity.acquire.cta.shared::cta.b64 P1, [%0], %1, 0x989680;\n\t" \
        "@P1 bra.uni WD_%=;\n\tbra.uni WL_%=;\n\tWD_%=:\n\t}"                 \
        :: "r"(a), "r"(ph) : "memory");                                       \
} while (0)
__device__ __forceinline__ void bulk_g2s(uint32_t dst, const void* src,
                                         uint32_t bytes, uint32_t mbar) {
    asm volatile(
        "cp.async.bulk.shared::cluster.global.mbarrier::complete_tx::bytes "
        "[%0], [%1], %2, [%3];"
        :: "r"(dst), "l"(src), "r"(bytes), "r"(mbar) : "memory");
}
__device__ __forceinline__ void mma_f16(float* d, const uint32_t* a,
                                        const uint32_t* b) {
    asm volatile(
        "mma.sync.aligned.m16n8k16.row.col.f32.f16.f16.f32 "
        "{%0,%1,%2,%3}, {%4,%5,%6,%7}, {%8,%9}, {%0,%1,%2,%3};\n"
        : "+f"(d[0]), "+f"(d[1]), "+f"(d[2]), "+f"(d[3])
        : "r"(a[0]), "r"(a[1]), "r"(a[2]), "r"(a[3]), "r"(b[0]), "r"(b[1]));
}
__device__ __forceinline__ void ldsm4(uint32_t* r, uint32_t addr) {
    asm volatile(
        "ldmatrix.sync.aligned.m8n8.x4.shared.b16 {%0,%1,%2,%3}, [%4];"
        : "=r"(r[0]), "=r"(r[1]), "=r"(r[2]), "=r"(r[3]) : "r"(addr));
}

#define N_STG 3

// ============== 2-term fp16 GEMM (R11-proven) ==============
// C[M,N] = A @ B^T; A hi/lo planes [M][K] kt-layout, B plane [N][K].
// CTA 128x128x64-per-stage, 16 warps (4x4), warp 32x32.
// acc += al*b; acc += ah*b
template <bool ADD, bool BIAS>
__device__ __forceinline__ void tc_core(
    const __half* __restrict__ AH, const __half* __restrict__ AL,
    const __half* __restrict__ B,
    const float* __restrict__ bias, float* __restrict__ C,
    int M, int N, int K) {
    extern __shared__ char smem[];
    constexpr uint32_t STG = 49152u;
    const int tid = threadIdx.x;
    const int lane = tid & 31;
    const int w = tid >> 5;
    const int wm = w & 3;
    const int wn = w >> 2;
    const int rowBase = blockIdx.y * 128;
    const int colBase = blockIdx.x * 128;
    const int ac = lane & 3;
    const int lr = lane >> 2;

    uint32_t sb = (uint32_t)__cvta_generic_to_shared(smem);
    uint32_t mb_full[N_STG] = { sb + 8, sb + 16, sb + 24 };

    if (tid == 0) {
        MBAR_INIT(mb_full[0], 1);
        MBAR_INIT(mb_full[1], 1);
        MBAR_INIT(mb_full[2], 1);
        asm volatile("fence.proxy.async.shared::cta;" ::: "memory");
    }
    __syncthreads();

    const int S = K >> 6;

    auto load_stage = [&](int s) {
        uint32_t d = sb + 1024 + (uint32_t)(s % N_STG) * STG;
        uint32_t fb = mb_full[s % N_STG];
        size_t aoff = ((size_t)s * (M >> 3) + (rowBase >> 3)) * 1024;
        size_t boff = ((size_t)s * (N >> 3) + (colBase >> 3)) * 1024;
        MBAR_EXPECT_TX(fb, STG);
        bulk_g2s(d, (const char*)AH + aoff, 16384, fb);
        bulk_g2s(d + 16384, (const char*)AL + aoff, 16384, fb);
        bulk_g2s(d + 32768, (const char*)B + boff, 16384, fb);
    };

    if (tid == 0) {
        load_stage(0);
        if (S > 1) load_stage(1);
        if (S > 2) load_stage(2);
    }

    const int lm = lane >> 3;
    const int rr = lane & 7;
    uint32_t aoffc[4], boffc[4];
#pragma unroll
    for (int c = 0; c < 4; c++) {
        uint32_t ao = (uint32_t)(rr * 128 + c * 32 + (lm >> 1) * 16);
        aoffc[c] = (uint32_t)((lm & 1) * 1024) + swz(ao);
        uint32_t bo = (uint32_t)(rr * 128 + c * 32 + (lm & 1) * 16);
        boffc[c] = (uint32_t)((lm >> 1) * 1024) + swz(bo);
    }

    float acc[2][4][4];
#pragma unroll
    for (int i = 0; i < 2; i++)
#pragma unroll
        for (int j = 0; j < 4; j++)
#pragma unroll
            for (int t = 0; t < 4; t++) acc[i][j][t] = 0.f;

    const uint32_t bB = (uint32_t)(wn * 4) * 1024;

    for (int s = 0; s < S; s++) {
        MBAR_WAIT(mb_full[s % N_STG], (s / N_STG) & 1);
        uint32_t stg = sb + 1024 + (uint32_t)(s % N_STG) * STG;
        uint32_t pAH = stg;
        uint32_t pAL = stg + 16384;
        uint32_t pB  = stg + 32768;

#pragma unroll
        for (int c = 0; c < 4; c++) {
            uint32_t bf[8];
            ldsm4(bf,     pB + bB + boffc[c]);
            ldsm4(bf + 4, pB + bB + 2048 + boffc[c]);
            uint32_t ah[2][4], al[2][4];
#pragma unroll
            for (int i = 0; i < 2; i++) {
                uint32_t aB = (uint32_t)(wm * 4 + i * 2) * 1024;
                ldsm4(ah[i], pAH + aB + aoffc[c]);
                ldsm4(al[i], pAL + aB + aoffc[c]);
            }
#pragma unroll
            for (int i = 0; i < 2; i++)
#pragma unroll
                for (int j = 0; j < 4; j++)
                    mma_f16(acc[i][j], al[i], bf + 2 * j);
#pragma unroll
            for (int i = 0; i < 2; i++)
#pragma unroll
                for (int j = 0; j < 4; j++)
                    mma_f16(acc[i][j], ah[i], bf + 2 * j);
        }
        __syncthreads();
        if (tid == 0 && s + N_STG < S) load_stage(s + N_STG);
    }

#pragma unroll
    for (int i = 0; i < 2; i++) {
        int r0 = rowBase + wm * 32 + i * 16 + lr;
#pragma unroll
        for (int j = 0; j < 4; j++) {
            int c0 = colBase + wn * 32 + j * 8 + ac * 2;
            float2 v0 = make_float2(acc[i][j][0], acc[i][j][1]);
            float2 v1 = make_float2(acc[i][j][2], acc[i][j][3]);
            if (BIAS) {
                float b0 = bias[c0], b1 = bias[c0 + 1];
                v0.x += b0; v0.y += b1; v1.x += b0; v1.y += b1;
            }
            float* p0 = C + (size_t)r0 * N + c0;
            float* p1 = C + (size_t)(r0 + 8) * N + c0;
            if (ADD) {
                float2 o0 = *(float2*)p0, o1 = *(float2*)p1;
                v0.x += o0.x; v0.y += o0.y;
                v1.x += o1.x; v1.y += o1.y;
            }
            *(float2*)p0 = v0;
            *(float2*)p1 = v1;
        }
    }
}

template <bool ADD, bool BIAS>
__global__ __launch_bounds__(512)
void tg_kernel(const __half* AH, const __half* AL, const __half* B,
               const float* bias, float* C, int M, int N, int K) {
    tc_core<ADD, BIAS>(AH, AL, B, bias, C, M, N, K);
}

__global__ __launch_bounds__(512)
void qkv_kernel(const __half* AH, const __half* AL,
                size_t oq, size_t ok, size_t ov,
                float* q, float* k, float* v) {
    size_t off = (blockIdx.z == 0) ? oq : (blockIdx.z == 1) ? ok : ov;
    float* C = (blockIdx.z == 0) ? q : (blockIdx.z == 1) ? k : v;
    tc_core<false, false>(AH, AL, g_wt + off, nullptr, C,
                          S_LEN, D_MODEL, D_MODEL);
}

// ============== fused W1||W3 + silu GEMM ==============
// f1 = hn@w1, f3 = hn@w3 in one CTA (shared A fragments); epilogue writes
// hsplit(silu(f1)*f3) directly to kt planes. stage = A_H|A_L|B1|B3, 3 stages.
__global__ __launch_bounds__(512)
void w13_fused_kernel(const __half* __restrict__ AH,
                      const __half* __restrict__ AL,
                      size_t o1, size_t o3,
                      __half* __restrict__ f1H, __half* __restrict__ f1L) {
    extern __shared__ char smem[];
    constexpr uint32_t STG = 65536u;
    const __half* B1 = g_wt + o1;
    const __half* B3 = g_wt + o3;
    const int tid = threadIdx.x;
    const int lane = tid & 31;
    const int w = tid >> 5;
    const int wm = w & 3;
    const int wn = w >> 2;
    const int rowBase = blockIdx.y * 128;
    const int colBase = blockIdx.x * 128;
    const int ac = lane & 3;
    const int lr = lane >> 2;
    const int M = S_LEN, N = FFN_DIM, K = D_MODEL;

    uint32_t sb = (uint32_t)__cvta_generic_to_shared(smem);
    uint32_t mb_full[N_STG] = { sb + 8, sb + 16, sb + 24 };

    if (tid == 0) {
        MBAR_INIT(mb_full[0], 1);
        MBAR_INIT(mb_full[1], 1);
        MBAR_INIT(mb_full[2], 1);
        asm volatile("fence.proxy.async.shared::cta;" ::: "memory");
    }
    __syncthreads();

    const int S = K >> 6;

    auto load_stage = [&](int s) {
        uint32_t d = sb + 1024 + (uint32_t)(s % N_STG) * STG;
        uint32_t fb = mb_full[s % N_STG];
        size_t aoff = ((size_t)s * (M >> 3) + (rowBase >> 3)) * 1024;
        size_t boff = ((size_t)s * (N >> 3) + (colBase >> 3)) * 1024;
        MBAR_EXPECT_TX(fb, STG);
        bulk_g2s(d, (const char*)AH + aoff, 16384, fb);
        bulk_g2s(d + 16384, (const char*)AL + aoff, 16384, fb);
        bulk_g2s(d + 32768, (const char*)B1 + boff, 16384, fb);
        bulk_g2s(d + 49152, (const char*)B3 + boff, 16384, fb);
    };

    if (tid == 0) {
        load_stage(0);
        load_stage(1);
        load_stage(2);
    }

    const int lm = lane >> 3;
    const int rr = lane & 7;
    uint32_t aoffc[4], boffc[4];
#pragma unroll
    for (int c = 0; c < 4; c++) {
        uint32_t ao = (uint32_t)(rr * 128 + c * 32 + (lm >> 1) * 16);
        aoffc[c] = (uint32_t)((lm & 1) * 1024) + swz(ao);
        uint32_t bo = (uint32_t)(rr * 128 + c * 32 + (lm & 1) * 16);
        boffc[c] = (uint32_t)((lm >> 1) * 1024) + swz(bo);
    }

    float acc1[2][4][4], acc3[2][4][4];
#pragma unroll
    for (int i = 0; i < 2; i++)
#pragma unroll
        for (int j = 0; j < 4; j++)
#pragma unroll
            for (int t = 0; t < 4; t++) { acc1[i][j][t] = 0.f; acc3[i][j][t] = 0.f; }

    const uint32_t bB = (uint32_t)(wn * 4) * 1024;

    for (int s = 0; s < S; s++) {
        MBAR_WAIT(mb_full[s % N_STG], (s / N_STG) & 1);
        uint32_t stg = sb + 1024 + (uint32_t)(s % N_STG) * STG;
        uint32_t pAH = stg;
        uint32_t pAL = stg + 16384;
        uint32_t pB1 = stg + 32768;
        uint32_t pB3 = stg + 49152;

#pragma unroll
        for (int c = 0; c < 4; c++) {
            uint32_t b1[8], b3[8];
            ldsm4(b1,     pB1 + bB + boffc[c]);
            ldsm4(b1 + 4, pB1 + bB + 2048 + boffc[c]);
            ldsm4(b3,     pB3 + bB + boffc[c]);
            ldsm4(b3 + 4, pB3 + bB + 2048 + boffc[c]);
            uint32_t ah[2][4], al[2][4];
#pragma unroll
            for (int i = 0; i < 2; i++) {
                uint32_t aB = (uint32_t)(wm * 4 + i * 2) * 1024;
                ldsm4(ah[i], pAH + aB + aoffc[c]);
                ldsm4(al[i], pAL + aB + aoffc[c]);
            }
#pragma unroll
            for (int i = 0; i < 2; i++)
#pragma unroll
                for (int j = 0; j < 4; j++) {
                    mma_f16(acc1[i][j], al[i], b1 + 2 * j);
                    mma_f16(acc3[i][j], al[i], b3 + 2 * j);
                }
#pragma unroll
            for (int i = 0; i < 2; i++)
#pragma unroll
                for (int j = 0; j < 4; j++) {
                    mma_f16(acc1[i][j], ah[i], b1 + 2 * j);
                    mma_f16(acc3[i][j], ah[i], b3 + 2 * j);
                }
        }
        __syncthreads();
        if (tid == 0 && s + N_STG < S) load_stage(s + N_STG);
    }

    // fused silu epilogue -> split planes
#pragma unroll
    for (int i = 0; i < 2; i++) {
        int r0 = rowBase + wm * 32 + i * 16 + lr;
#pragma unroll
        for (int j = 0; j < 4; j++) {
            int c0 = colBase + wn * 32 + j * 8 + ac * 2;
#pragma unroll
            for (int half = 0; half < 2; half++) {
                int rr2 = r0 + half * 8;
                float a0 = acc1[i][j][half * 2];
                float a1 = acc1[i][j][half * 2 + 1];
                float v0 = (a0 / (1.f + expf(-a0))) * acc3[i][j][half * 2];
                float v1 = (a1 / (1.f + expf(-a1))) * acc3[i][j][half * 2 + 1];
                __half h0, l0, h1, l1;
                hsplit(v0, h0, l0);
                hsplit(v1, h1, l1);
                size_t a = kt_addr(rr2, c0, S_LEN);
                *(__half2*)((char*)f1H + a) = __halves2half2(h0, h1);
                *(__half2*)((char*)f1L + a) = __halves2half2(l0, l1);
            }
        }
    }
}

// ---------------- weight transpose into kt layout ----------------
// src [K,N] fp32 -> dst fp16 plane [N][K] kt layout. 64x64 tiles.
// Global reads/writes are 16B vector; smem scatter is scalar (stride-65 rows,
// so float4 smem stores would be misaligned — that was the R16 crash).
__global__ __launch_bounds__(256)
void transpose_kt(const float* __restrict__ src, __half* __restrict__ dst,
                  int K, int N, size_t srcStride, size_t dstStride) {
    src += (size_t)blockIdx.z * srcStride;
    dst += (size_t)blockIdx.z * dstStride;
    __shared__ float t[64][65];
    const int tid = threadIdx.x;
    const int x0 = blockIdx.x * 64;
    const int y0 = blockIdx.y * 64;
    const int nx = (tid & 15) * 4;
#pragma unroll
    for (int i = 0; i < 4; i++) {
        int kl = (tid >> 4) + i * 16;
        float4 vsrc = *(const float4*)&src[(size_t)(y0 + kl) * N + x0 + nx];
        t[kl][nx + 0] = vsrc.x;
        t[kl][nx + 1] = vsrc.y;
        t[kl][nx + 2] = vsrc.z;
        t[kl][nx + 3] = vsrc.w;
    }
    __syncthreads();
#pragma unroll
    for (int it = 0; it < 2; it++) {
        int item = tid + it * 256;
        int nl = item >> 3;
        int ck = item & 7;
        uint4 wv;
        uint32_t* wp = (uint32_t*)&wv;
#pragma unroll
        for (int e = 0; e < 4; e++)
            wp[e] = pack2h(t[ck * 8 + 2 * e][nl], t[ck * 8 + 2 * e + 1][nl]);
        int n = x0 + nl;
        size_t a = ((size_t)(y0 >> 6) * (N >> 3) + (n >> 3)) * 1024 +
                   swz((uint32_t)((n & 7) * 128 + ck * 16));
        *(uint4*)((char*)dst + a) = wv;
    }
}

// ---------------- x split (vectorized) ----------------
__global__ __launch_bounds__(256)
void x_split_kernel(const float* __restrict__ x) {
    int item = blockIdx.x * 256 + threadIdx.x;     // S_LEN*8 items
    if (item >= S_LEN * 8) return;
    int row = item >> 3;
    int ck = item & 7;
    const float* xp = x + (size_t)row * IN_DIM + ck * 8;
    uint4 hv, lv;
    uint32_t* hp = (uint32_t*)&hv;
    uint32_t* lp = (uint32_t*)&lv;
#pragma unroll
    for (int e = 0; e < 4; e++) {
        __half h0, l0, h1, l1;
        hsplit(xp[2 * e], h0, l0);
        hsplit(xp[2 * e + 1], h1, l1);
        hp[e] = ((uint32_t)__half_as_ushort(h0)) | ((uint32_t)__half_as_ushort(h1) << 16);
        lp[e] = ((uint32_t)__half_as_ushort(l0)) | ((uint32_t)__half_as_ushort(l1) << 16);
    }
    size_t a = ((size_t)(row >> 3)) * 1024 + swz((uint32_t)((row & 7) * 128 + ck * 16));
    *(uint4*)((char*)g_xH + a) = hv;
    *(uint4*)((char*)g_xL + a) = lv;
}

// ---------------- RMSNorm -> split planes (vectorized writes) ----------
__global__ __launch_bounds__(256)
void rmsnorm_split_kernel(const float* __restrict__ x,
                          const float* __restrict__ w,
                          __half* __restrict__ yH,
                          __half* __restrict__ yL) {
    int row = blockIdx.x;
    const float* xr = x + (size_t)row * D_MODEL;
    float s = 0.f;
    for (int i = threadIdx.x; i < D_MODEL; i += 256) {
        float v = xr[i];
        s += v * v;
    }
    __shared__ float red[8];
#pragma unroll
    for (int o = 16; o; o >>= 1) s += __shfl_xor_sync(0xffffffffu, s, o);
    if ((threadIdx.x & 31) == 0) red[threadIdx.x >> 5] = s;
    __syncthreads();
    if (threadIdx.x < 8) {
        float t = red[threadIdx.x];
#pragma unroll
        for (int o = 4; o; o >>= 1) t += __shfl_xor_sync(0xffu, t, o);
        if (threadIdx.x == 0) red[0] = rsqrtf(t / (float)D_MODEL + 1e-5f);
    }
    __syncthreads();
    float r = red[0];
    if (threadIdx.x < 128) {
        int k0 = threadIdx.x * 8;
        uint4 hv, lv;
        uint32_t* hp = (uint32_t*)&hv;
        uint32_t* lp = (uint32_t*)&lv;
#pragma unroll
        for (int e = 0; e < 4; e++) {
            float v0 = xr[k0 + 2 * e] * r * w[k0 + 2 * e];
            float v1 = xr[k0 + 2 * e + 1] * r * w[k0 + 2 * e + 1];
            __half h0, l0, h1, l1;
            hsplit(v0, h0, l0);
            hsplit(v1, h1, l1);
            hp[e] = ((uint32_t)__half_as_ushort(h0)) | ((uint32_t)__half_as_ushort(h1) << 16);
            lp[e] = ((uint32_t)__half_as_ushort(l0)) | ((uint32_t)__half_as_ushort(l1) << 16);
        }
        size_t a = ((size_t)(k0 >> 6) * (S_LEN >> 3) + (row >> 3)) * 1024 +
                   swz((uint32_t)((row & 7) * 128 + (k0 & 63) * 2));
        *(uint4*)((char*)yH + a) = hv;
        *(uint4*)((char*)yL + a) = lv;
    }
}

// ---------------- RoPE (in place on q and k) ----------------
__global__ __launch_bounds__(256)
void rope_kernel(float* __restrict__ q, float* __restrict__ k,
                 const int* __restrict__ tok_id) {
    int idx = blockIdx.x * 256 + threadIdx.x;
    if (idx >= S_LEN * N_HEADS * (HEAD_DIM / 2)) return;
    int j = idx & 31;
    int h = (idx >> 5) & 15;
    int s = idx >> 9;
    float t = (float)tok_id[s];
    float inv = expf(-logf(10000.f) * (float)(2 * j) / (float)HEAD_DIM);
    float ang = t * inv;
    float c = cosf(ang), sn = sinf(ang);
    int base = s * D_MODEL + h * HEAD_DIM + j;
    float q1 = q[base], q2 = q[base + 32];
    q[base] = q1 * c - q2 * sn;
    q[base + 32] = q1 * sn + q2 * c;
    float k1 = k[base], k2 = k[base + 32];
    k[base] = k1 * c - k2 * sn;
    k[base + 32] = k1 * sn + k2 * c;
}

// ---------------- attention -> split planes (vectorized writes) --------
__global__ __launch_bounds__(256)
void attention_kernel(const float* __restrict__ q, const float* __restrict__ k,
                      const float* __restrict__ v,
                      __half* __restrict__ outH,
                      __half* __restrict__ outL) {
    const int doc = blockIdx.x;
    const int head = blockIdx.y;
    const int qi = threadIdx.x;
    const int qg = doc * DOC_LEN + qi;

    __shared__ float Ks[64][64];
    __shared__ float Vs[64][64];

    float qreg[HEAD_DIM];
    const float scale = 0.125f;
    const float* qp = q + (size_t)qg * D_MODEL + head * HEAD_DIM;
#pragma unroll
    for (int d = 0; d < HEAD_DIM; d += 4) {
        float4 t = *(const float4*)&qp[d];
        qreg[d] = t.x * scale; qreg[d + 1] = t.y * scale;
        qreg[d + 2] = t.z * scale; qreg[d + 3] = t.w * scale;
    }

    float o[HEAD_DIM];
#pragma unroll
    for (int d = 0; d < HEAD_DIM; d++) o[d] = 0.f;
    float m = -1e30f, l = 0.f;

    for (int kt = 0; kt < 4; kt++) {
        __syncthreads();
        for (int f = threadIdx.x; f < 1024; f += 256) {
            int r = f >> 4;
            int c = (f & 15) << 2;
            int kg = doc * DOC_LEN + kt * 64 + r;
            *(float4*)&Ks[r][c] =
                *(const float4*)&k[(size_t)kg * D_MODEL + head * HEAD_DIM + c];
            *(float4*)&Vs[r][c] =
                *(const float4*)&v[(size_t)kg * D_MODEL + head * HEAD_DIM + c];
        }
        __syncthreads();

        for (int j = 0; j < 64; j++) {
            int tk = kt * 64 + j;
            int dlt = qi - tk;
            if (dlt < 0) dlt = -dlt;
            if (dlt < WIN) {
                float s = 0.f;
#pragma unroll
                for (int d = 0; d < HEAD_DIM; d++) s += qreg[d] * Ks[j][d];
                float mn = fmaxf(m, s);
                float corr = expf(m - mn);
                float p = expf(s - mn);
                l = l * corr + p;
#pragma unroll
                for (int d = 0; d < HEAD_DIM; d++)
                    o[d] = o[d] * corr + p * Vs[j][d];
                m = mn;
            }
        }
    }

    float invl = 1.f / l;
    size_t abase = ((size_t)head * (S_LEN >> 3) + (qg >> 3)) * 1024;
#pragma unroll
    for (int ck = 0; ck < 8; ck++) {
        uint4 hv, lv;
        uint32_t* hp = (uint32_t*)&hv;
        uint32_t* lp = (uint32_t*)&lv;
#pragma unroll
        for (int e = 0; e < 4; e++) {
            __half h0, l0, h1, l1;
            hsplit(o[ck * 8 + 2 * e] * invl, h0, l0);
            hsplit(o[ck * 8 + 2 * e + 1] * invl, h1, l1);
            hp[e] = ((uint32_t)__half_as_ushort(h0)) | ((uint32_t)__half_as_ushort(h1) << 16);
            lp[e] = ((uint32_t)__half_as_ushort(l0)) | ((uint32_t)__half_as_ushort(l1) << 16);
        }
        uint32_t off = swz((uint32_t)((qg & 7) * 128 + ck * 16));
        *(uint4*)((char*)outH + abase + off) = hv;
        *(uint4*)((char*)outL + abase + off) = lv;
    }
}

// ---------------- host orchestration ----------------
extern "C" void kernel_launch(void* const* d_in, const int* in_sizes, int n_in,
                              void* d_out, int out_size) {
    const float* x           = (const float*)d_in[0];
    const float* emb_w       = (const float*)d_in[1];
    const float* emb_b       = (const float*)d_in[2];
    const float* wq          = (const float*)d_in[3];
    const float* wk          = (const float*)d_in[4];
    const float* wv          = (const float*)d_in[5];
    const float* wo          = (const float*)d_in[6];
    const float* attn_norm_w = (const float*)d_in[7];
    const float* ffn_norm_w  = (const float*)d_in[8];
    const float* w1          = (const float*)d_in[9];
    const float* w2          = (const float*)d_in[10];
    const float* w3          = (const float*)d_in[11];
    const float* out_norm_w  = (const float*)d_in[12];
    const float* out_w       = (const float*)d_in[13];
    const int*   tok_id      = (const int*)d_in[15];
    float* out = (float*)d_out;

    float *h, *q, *k, *v;
    cudaGetSymbolAddress((void**)&h, g_h);
    cudaGetSymbolAddress((void**)&q, g_q);
    cudaGetSymbolAddress((void**)&k, g_k);
    cudaGetSymbolAddress((void**)&v, g_v);
    __half *wt, *xH, *xL, *hnH, *hnL, *attH, *attL, *f1H, *f1L;
    cudaGetSymbolAddress((void**)&wt, g_wt);
    cudaGetSymbolAddress((void**)&xH, g_xH);
    cudaGetSymbolAddress((void**)&xL, g_xL);
    cudaGetSymbolAddress((void**)&hnH, g_hnH);
    cudaGetSymbolAddress((void**)&hnL, g_hnL);
    cudaGetSymbolAddress((void**)&attH, g_attH);
    cudaGetSymbolAddress((void**)&attL, g_attL);
    cudaGetSymbolAddress((void**)&f1H, g_f1H);
    cudaGetSymbolAddress((void**)&f1L, g_f1L);

    const int SMT2 = 1024 + N_STG * 49152;   // 148480 (2-term GEMM)
    const int SMT4 = 1024 + N_STG * 65536;   // 197632 (fused w13)
    cudaFuncSetAttribute(tg_kernel<false, true>,
                         cudaFuncAttributeMaxDynamicSharedMemorySize, SMT2);
    cudaFuncSetAttribute(tg_kernel<true, false>,
                         cudaFuncAttributeMaxDynamicSharedMemorySize, SMT2);
    cudaFuncSetAttribute(tg_kernel<false, false>,
                         cudaFuncAttributeMaxDynamicSharedMemorySize, SMT2);
    cudaFuncSetAttribute(qkv_kernel,
                         cudaFuncAttributeMaxDynamicSharedMemorySize, SMT2);
    cudaFuncSetAttribute(w13_fused_kernel,
                         cudaFuncAttributeMaxDynamicSharedMemorySize, SMT4);

    // weight prepass
    transpose_kt<<<dim3(16, 16, 4), 256>>>(wq, wt + OFF_WQ,
        D_MODEL, D_MODEL, (size_t)D_MODEL * D_MODEL, 1048576ULL);
    transpose_kt<<<dim3(16, 16, 4), 256>>>(wk, wt + OFF_WK,
        D_MODEL, D_MODEL, (size_t)D_MODEL * D_MODEL, 1048576ULL);
    transpose_kt<<<dim3(16, 16, 4), 256>>>(wv, wt + OFF_WV,
        D_MODEL, D_MODEL, (size_t)D_MODEL * D_MODEL, 1048576ULL);
    transpose_kt<<<dim3(16, 16, 4), 256>>>(wo, wt + OFF_WO,
        D_MODEL, D_MODEL, (size_t)D_MODEL * D_MODEL, 1048576ULL);
    transpose_kt<<<dim3(64, 16, 4), 256>>>(w1, wt + OFF_W1,
        D_MODEL, FFN_DIM, (size_t)D_MODEL * FFN_DIM, 4194304ULL);
    transpose_kt<<<dim3(64, 16, 4), 256>>>(w3, wt + OFF_W3,
        D_MODEL, FFN_DIM, (size_t)D_MODEL * FFN_DIM, 4194304ULL);
    transpose_kt<<<dim3(16, 64, 4), 256>>>(w2, wt + OFF_W2,
        FFN_DIM, D_MODEL, (size_t)FFN_DIM * D_MODEL, 4194304ULL);
    transpose_kt<<<dim3(16, 1, 1), 256>>>(emb_w, wt + OFF_EMB,
        IN_DIM, D_MODEL, 0ULL, 0ULL);
    transpose_kt<<<dim3(2, 16, 1), 256>>>(out_w, wt + OFF_OUT,
        D_MODEL, OUT_DIM, 0ULL, 0ULL);

    x_split_kernel<<<(S_LEN * 8 + 255) / 256, 256>>>(x);

    // embed: h = x @ emb_w + emb_b
    tg_kernel<false, true><<<dim3(8, 16), 512, SMT2>>>(
        xH, xL, wt + OFF_EMB, emb_b, h, S_LEN, D_MODEL, IN_DIM);

    for (int l = 0; l < N_LAYERS; l++) {
        size_t oq = OFF_WQ + (size_t)l * 1048576;
        size_t ok = OFF_WK + (size_t)l * 1048576;
        size_t ov = OFF_WV + (size_t)l * 1048576;
        size_t oo = OFF_WO + (size_t)l * 1048576;
        size_t o1 = OFF_W1 + (size_t)l * 4194304;
        size_t o3 = OFF_W3 + (size_t)l * 4194304;
        size_t o2 = OFF_W2 + (size_t)l * 4194304;

        rmsnorm_split_kernel<<<S_LEN, 256>>>(h, attn_norm_w + l * D_MODEL,
                                             hnH, hnL);

        qkv_kernel<<<dim3(8, 16, 3), 512, SMT2>>>(hnH, hnL, oq, ok, ov,
                                                  q, k, v);

        rope_kernel<<<(S_LEN * N_HEADS * 32) / 256, 256>>>(q, k, tok_id);

        attention_kernel<<<dim3(N_DOCS, N_HEADS), 256>>>(q, k, v, attH, attL);

        tg_kernel<true, false><<<dim3(8, 16), 512, SMT2>>>(
            attH, attL, wt + oo, nullptr, h, S_LEN, D_MODEL, D_MODEL);

        rmsnorm_split_kernel<<<S_LEN, 256>>>(h, ffn_norm_w + l * D_MODEL,
                                             hnH, hnL);

        w13_fused_kernel<<<dim3(32, 16), 512, SMT4>>>(hnH, hnL, o1, o3,
                                                      f1H, f1L);

        tg_kernel<true, false><<<dim3(8, 16), 512, SMT2>>>(
            f1H, f1L, wt + o2, nullptr, h, S_LEN, D_MODEL, FFN_DIM);
    }

    rmsnorm_split_kernel<<<S_LEN, 256>>>(h, out_norm_w, hnH, hnL);
    tg_kernel<false, false><<<dim3(1, 16), 512, SMT2>>>(
        hnH, hnL, wt + OFF_OUT, nullptr, out, S_LEN, OUT_DIM, D_MODEL);
}